// round 3
// baseline (speedup 1.0000x reference)
#include <cuda_runtime.h>
#include <cuda_bf16.h>
#include <math.h>
#include <stdint.h>

// Problem constants
#define B_SZ   2
#define T_SEQ  2048
#define C_DIM  1024
#define C3     3072
#define NH     16
#define DH     64
#define MEMLEN 1024
#define M_TOT  (B_SZ * T_SEQ)   // 4096

// Scratch (no cudaMalloc allowed)
__device__ float g_qkv[(size_t)M_TOT * C3];   // 48 MB
__device__ float g_y[(size_t)M_TOT * C_DIM];  // 16 MB

// ---------------------------------------------------------------------------
// helpers
// ---------------------------------------------------------------------------
__device__ __forceinline__ uint32_t sptr(const void* p) {
    return (uint32_t)__cvta_generic_to_shared(p);
}

__device__ __forceinline__ void ldm4(uint32_t r[4], uint32_t a) {
    asm volatile("ldmatrix.sync.aligned.m8n8.x4.shared.b16 {%0,%1,%2,%3},[%4];\n"
                 : "=r"(r[0]), "=r"(r[1]), "=r"(r[2]), "=r"(r[3]) : "r"(a));
}

__device__ __forceinline__ void mma8(float d[4], const uint32_t a[4],
                                     uint32_t b0, uint32_t b1) {
    asm volatile(
        "mma.sync.aligned.m16n8k8.row.col.f32.tf32.tf32.f32 "
        "{%0,%1,%2,%3},{%4,%5,%6,%7},{%8,%9},{%0,%1,%2,%3};\n"
        : "+f"(d[0]), "+f"(d[1]), "+f"(d[2]), "+f"(d[3])
        : "r"(a[0]), "r"(a[1]), "r"(a[2]), "r"(a[3]), "r"(b0), "r"(b1));
}

__device__ __forceinline__ float tf32hi(float x) {
    uint32_t u;
    asm("cvt.rna.tf32.f32 %0, %1;" : "=r"(u) : "f"(x));
    return __uint_as_float(u);
}

// ---------------------------------------------------------------------------
// TF32 NT GEMM: C[M,N] = A[M,K] * B[N,K]^T
// 128x128x32 tile, 256 threads (8 warps, 2Mx4N, each 64x32).
// Blocks with n0 < fullN use 3x-tf32 (fp32-accurate); others single-pass.
// Smem rows: 32 floats (8 x 16B chunks) padded to 36 floats, 16B-chunk XOR swizzle.
// ---------------------------------------------------------------------------
#define GRS 36           // row stride in floats
#define GRSB 144         // row stride bytes
#define GEMM_SMEM (4 * 128 * GRS * 4)

__global__ __launch_bounds__(256)
void gemm_tf32(const float* __restrict__ A, const float* __restrict__ Bm,
               float* __restrict__ C, int N, int K, int fullN)
{
    extern __shared__ float gs[];
    float* Ah = gs;
    float* Al = Ah + 128 * GRS;
    float* Bh = Al + 128 * GRS;
    float* Bl = Bh + 128 * GRS;

    const int tid = threadIdx.x, lane = tid & 31, warp = tid >> 5;
    const int m0 = blockIdx.y * 128, n0 = blockIdx.x * 128;
    const bool full = (n0 < fullN);
    const int mbase = (warp & 1) * 64, nbase = (warp >> 1) * 32;

    const int L = lane;
    const int arow = mbase + (L & 7) + 8 * ((L >> 3) & 1);
    const int ac   = L >> 4;
    const int brow = nbase + (L & 7) + 8 * (L >> 4);
    const int bc   = (L >> 3) & 1;
    const int swz  = L & 7;
    const uint32_t sAh = sptr(Ah) + arow * GRSB;
    const uint32_t sAl = sptr(Al) + arow * GRSB;
    const uint32_t sBh = sptr(Bh) + brow * GRSB;
    const uint32_t sBl = sptr(Bl) + brow * GRSB;

    // loader mapping: thread -> (row, 4 chunks)
    const int lrow = tid >> 1, lc4 = (tid & 1) * 4;
    const float* ag = A  + (size_t)(m0 + lrow) * K + lc4 * 4;
    const float* bg = Bm + (size_t)(n0 + lrow) * K + lc4 * 4;
    const int ldst = lrow * GRS;
    const int lswz = lrow & 7;

    float acc[4][4][4] = {};

    for (int k0 = 0; k0 < K; k0 += 32) {
#pragma unroll
        for (int i = 0; i < 4; i++) {
            int ch = lc4 + i;
            int di = ldst + ((ch ^ lswz) << 2);
            float4 va = *(const float4*)(ag + k0 + i * 4);
            float4 ha, la;
            ha.x = tf32hi(va.x); la.x = tf32hi(va.x - ha.x);
            ha.y = tf32hi(va.y); la.y = tf32hi(va.y - ha.y);
            ha.z = tf32hi(va.z); la.z = tf32hi(va.z - ha.z);
            ha.w = tf32hi(va.w); la.w = tf32hi(va.w - ha.w);
            *(float4*)(Ah + di) = ha; *(float4*)(Al + di) = la;
            float4 vb = *(const float4*)(bg + k0 + i * 4);
            float4 hb, lb;
            hb.x = tf32hi(vb.x); lb.x = tf32hi(vb.x - hb.x);
            hb.y = tf32hi(vb.y); lb.y = tf32hi(vb.y - hb.y);
            hb.z = tf32hi(vb.z); lb.z = tf32hi(vb.z - hb.z);
            hb.w = tf32hi(vb.w); lb.w = tf32hi(vb.w - hb.w);
            *(float4*)(Bh + di) = hb; *(float4*)(Bl + di) = lb;
        }
        __syncthreads();

#pragma unroll
        for (int s = 0; s < 4; s++) {
            const uint32_t chA = (uint32_t)((((2 * s + ac) ^ swz)) << 4);
            const uint32_t chB = (uint32_t)((((2 * s + bc) ^ swz)) << 4);
            uint32_t b0[4], b1[4], l0[4], l1[4];
            ldm4(b0, sBh + chB);
            ldm4(b1, sBh + 16 * GRSB + chB);
            if (full) {
                ldm4(l0, sBl + chB);
                ldm4(l1, sBl + 16 * GRSB + chB);
            }
#pragma unroll
            for (int fm = 0; fm < 4; fm++) {
                uint32_t a[4];
                ldm4(a, sAh + fm * 16 * GRSB + chA);
                mma8(acc[fm][0], a, b0[0], b0[1]);
                mma8(acc[fm][1], a, b0[2], b0[3]);
                mma8(acc[fm][2], a, b1[0], b1[1]);
                mma8(acc[fm][3], a, b1[2], b1[3]);
                if (full) {
                    mma8(acc[fm][0], a, l0[0], l0[1]);
                    mma8(acc[fm][1], a, l0[2], l0[3]);
                    mma8(acc[fm][2], a, l1[0], l1[1]);
                    mma8(acc[fm][3], a, l1[2], l1[3]);
                    uint32_t al[4];
                    ldm4(al, sAl + fm * 16 * GRSB + chA);
                    mma8(acc[fm][0], al, b0[0], b0[1]);
                    mma8(acc[fm][1], al, b0[2], b0[3]);
                    mma8(acc[fm][2], al, b1[0], b1[1]);
                    mma8(acc[fm][3], al, b1[2], b1[3]);
                }
            }
        }
        __syncthreads();
    }

    const int er = lane >> 2, ec = (lane & 3) * 2;
#pragma unroll
    for (int fm = 0; fm < 4; fm++)
#pragma unroll
        for (int fn = 0; fn < 4; fn++) {
            int r = m0 + mbase + fm * 16 + er;
            int c = n0 + nbase + fn * 8 + ec;
            *(float2*)(C + (size_t)r * N + c)       = make_float2(acc[fm][fn][0], acc[fm][fn][1]);
            *(float2*)(C + (size_t)(r + 8) * N + c) = make_float2(acc[fm][fn][2], acc[fm][fn][3]);
        }
}

// ---------------------------------------------------------------------------
// Fused flash attention with tensor-core mma.
// Block = (qtile 64, head, batch), 256 threads (8 warps, 2Mx4N).
// S = QK^T in 3x-tf32 (logit-accurate); P@V single tf32.
// Smem rows: 64 floats (16 chunks) padded to 68 floats, chunk XOR swizzle.
// ---------------------------------------------------------------------------
#define ARS 68           // attention row stride floats
#define ARSB 272         // bytes
#define ATILE (64 * ARS) // floats per tile buffer
#define ATTN_SMEM ((6 * ATILE + 4 * 64) * 4)

__global__ __launch_bounds__(256)
void attn_mma_kernel(const float* __restrict__ qm,
                     const float* __restrict__ qkv, float* __restrict__ y)
{
    extern __shared__ float smf[];
    float* Qh = smf;
    float* Ql = Qh + ATILE;
    float* Kh = Ql + ATILE;
    float* Kl = Kh + ATILE;
    float* Vt = Kl + ATILE;
    float* Ss = Vt + ATILE;
    float* mrow = Ss + ATILE;
    float* lrow = mrow + 64;
    float* frow = lrow + 64;
    float* qsc  = frow + 64;

    const int qt = blockIdx.x, h = blockIdx.y, b = blockIdx.z;
    const int q0 = qt * 64;
    const int tid = threadIdx.x, lane = tid & 31, warp = tid >> 5;

    if (tid < 64) {
        qsc[tid] = logf(2048.0f) * qm[tid] * rsqrtf(64.0f);
        mrow[tid] = -1e30f;
        lrow[tid] = 0.0f;
    }
    __syncthreads();

    // Load + scale Q tile (hi/lo split)
    const float* qg = qkv + (size_t)(b * T_SEQ + q0) * C3 + h * DH;
    {
        int row = tid >> 2, c4 = (tid & 3) * 4;
        const float* src = qg + (size_t)row * C3 + c4 * 4;
#pragma unroll
        for (int i = 0; i < 4; i++) {
            int ch = c4 + i;
            int di = row * ARS + ((ch ^ (row & 7)) << 2);
            float4 v = *(const float4*)(src + i * 4);
            v.x *= qsc[ch * 4 + 0]; v.y *= qsc[ch * 4 + 1];
            v.z *= qsc[ch * 4 + 2]; v.w *= qsc[ch * 4 + 3];
            float4 hi, lo;
            hi.x = tf32hi(v.x); lo.x = tf32hi(v.x - hi.x);
            hi.y = tf32hi(v.y); lo.y = tf32hi(v.y - hi.y);
            hi.z = tf32hi(v.z); lo.z = tf32hi(v.z - hi.z);
            hi.w = tf32hi(v.w); lo.w = tf32hi(v.w - hi.w);
            *(float4*)(Qh + di) = hi; *(float4*)(Ql + di) = lo;
        }
    }

    const int mq = (warp & 1) * 32;        // q offset of warp
    const int nb = (warp >> 1) * 16;       // kv (or d) offset of warp
    const int L = lane;
    const int arow = mq + (L & 7) + 8 * ((L >> 3) & 1);
    const int ac   = L >> 4;
    const int brow = nb + (L & 7) + 8 * (L >> 4);
    const int bc   = (L >> 3) & 1;
    const int swz  = L & 7;
    const uint32_t sQh = sptr(Qh) + arow * ARSB;
    const uint32_t sQl = sptr(Ql) + arow * ARSB;
    const uint32_t sKh = sptr(Kh) + brow * ARSB;
    const uint32_t sKl = sptr(Kl) + brow * ARSB;
    const uint32_t sVt = sptr(Vt) + brow * ARSB;
    const uint32_t sSs = sptr(Ss) + arow * ARSB;

    float acc[2][2][4] = {};

    const int maxc = (q0 + 64 > MEMLEN) ? (q0 + 64) : MEMLEN;
    const int nT = maxc / 64;
    const float* kg = qkv + (size_t)(b * T_SEQ) * C3 + C_DIM + h * DH;
    const float* vg = kg + C_DIM;

    for (int t = 0; t < nT; t++) {
        const int kj0 = t * 64;
        __syncthreads();  // protect K/V/S smem reuse from previous iteration

        // Load K (hi/lo) and V (transposed, tf32)
        {
            int row = tid >> 2, c4 = (tid & 3) * 4;
            const float* ks = kg + (size_t)(kj0 + row) * C3 + c4 * 4;
            const float* vs = vg + (size_t)(kj0 + row) * C3 + c4 * 4;
            int rx = row & 7;
#pragma unroll
            for (int i = 0; i < 4; i++) {
                int ch = c4 + i;
                int di = row * ARS + ((ch ^ rx) << 2);
                float4 v = *(const float4*)(ks + i * 4);
                float4 hi, lo;
                hi.x = tf32hi(v.x); lo.x = tf32hi(v.x - hi.x);
                hi.y = tf32hi(v.y); lo.y = tf32hi(v.y - hi.y);
                hi.z = tf32hi(v.z); lo.z = tf32hi(v.z - hi.z);
                hi.w = tf32hi(v.w); lo.w = tf32hi(v.w - hi.w);
                *(float4*)(Kh + di) = hi; *(float4*)(Kl + di) = lo;
                float4 w = *(const float4*)(vs + i * 4);
                float wv[4] = {w.x, w.y, w.z, w.w};
#pragma unroll
                for (int j = 0; j < 4; j++) {
                    int d = ch * 4 + j;
                    Vt[d * ARS + (((row >> 2) ^ (d & 7)) << 2) + (row & 3)] = tf32hi(wv[j]);
                }
            }
        }
        __syncthreads();

        // S = Q K^T  (3x tf32)
        float s_[2][2][4] = {};
#pragma unroll
        for (int s = 0; s < 8; s++) {
            uint32_t chA = (uint32_t)(((2 * s + ac) ^ swz) << 4);
            uint32_t chB = (uint32_t)(((2 * s + bc) ^ swz) << 4);
            uint32_t kh[4], kl[4];
            ldm4(kh, sKh + chB);
            ldm4(kl, sKl + chB);
#pragma unroll
            for (int fm = 0; fm < 2; fm++) {
                uint32_t qh_[4], ql_[4];
                ldm4(qh_, sQh + fm * 16 * ARSB + chA);
                mma8(s_[fm][0], qh_, kh[0], kh[1]);
                mma8(s_[fm][1], qh_, kh[2], kh[3]);
                mma8(s_[fm][0], qh_, kl[0], kl[1]);
                mma8(s_[fm][1], qh_, kl[2], kl[3]);
                ldm4(ql_, sQl + fm * 16 * ARSB + chA);
                mma8(s_[fm][0], ql_, kh[0], kh[1]);
                mma8(s_[fm][1], ql_, kh[2], kh[3]);
            }
        }

        // mask + store S to smem
        {
            const bool needMask = (kj0 >= MEMLEN);
            const int er = lane >> 2, ec = (lane & 3) * 2;
#pragma unroll
            for (int fm = 0; fm < 2; fm++)
#pragma unroll
                for (int fn = 0; fn < 2; fn++) {
                    int r = mq + fm * 16 + er;
                    int cc = nb + fn * 8 + ec;
                    float2 v01 = make_float2(s_[fm][fn][0], s_[fm][fn][1]);
                    float2 v23 = make_float2(s_[fm][fn][2], s_[fm][fn][3]);
                    if (needMask) {
                        int gr = q0 + r, gc = kj0 + cc;
                        if (gc > gr) v01.x = -1e30f;
                        if (gc + 1 > gr) v01.y = -1e30f;
                        if (gc > gr + 8) v23.x = -1e30f;
                        if (gc + 1 > gr + 8) v23.y = -1e30f;
                    }
                    int chk = cc >> 2, wi = cc & 3;
                    int sw = ((chk ^ (r & 7)) << 2) + wi;
                    *(float2*)(Ss + r * ARS + sw) = v01;
                    *(float2*)(Ss + (r + 8) * ARS + sw) = v23;
                }
        }
        __syncthreads();

        // online softmax (rows of 64, 4 threads/row, swizzle-aware)
        {
            int row = tid >> 2, part = tid & 3;
            float* rp = Ss + row * ARS;
            int rx = row & 7;
            float vbuf[16];
            float mx = -1e30f;
#pragma unroll
            for (int i = 0; i < 4; i++) {
                int ch = part * 4 + i;
                float4 v = *(const float4*)(rp + ((ch ^ rx) << 2));
                vbuf[i * 4 + 0] = v.x; vbuf[i * 4 + 1] = v.y;
                vbuf[i * 4 + 2] = v.z; vbuf[i * 4 + 3] = v.w;
                mx = fmaxf(mx, fmaxf(fmaxf(v.x, v.y), fmaxf(v.z, v.w)));
            }
            mx = fmaxf(mx, __shfl_xor_sync(0xffffffffu, mx, 1));
            mx = fmaxf(mx, __shfl_xor_sync(0xffffffffu, mx, 2));
            float mold = mrow[row];
            float mnew = fmaxf(mold, mx);
            float lsum = 0.0f;
#pragma unroll
            for (int i = 0; i < 4; i++) {
                int ch = part * 4 + i;
                float4 v;
                v.x = tf32hi(__expf(vbuf[i * 4 + 0] - mnew));
                v.y = tf32hi(__expf(vbuf[i * 4 + 1] - mnew));
                v.z = tf32hi(__expf(vbuf[i * 4 + 2] - mnew));
                v.w = tf32hi(__expf(vbuf[i * 4 + 3] - mnew));
                lsum += v.x + v.y + v.z + v.w;
                *(float4*)(rp + ((ch ^ rx) << 2)) = v;
            }
            lsum += __shfl_xor_sync(0xffffffffu, lsum, 1);
            lsum += __shfl_xor_sync(0xffffffffu, lsum, 2);
            if (part == 0) {
                float fc = __expf(mold - mnew);
                mrow[row] = mnew;
                frow[row] = fc;
                lrow[row] = lrow[row] * fc + lsum;
            }
        }
        __syncthreads();

        // rescale + P@V (single tf32)
        {
            int er = lane >> 2;
#pragma unroll
            for (int fm = 0; fm < 2; fm++) {
                float f0 = frow[mq + fm * 16 + er];
                float f1 = frow[mq + fm * 16 + 8 + er];
#pragma unroll
                for (int fn = 0; fn < 2; fn++) {
                    acc[fm][fn][0] *= f0; acc[fm][fn][1] *= f0;
                    acc[fm][fn][2] *= f1; acc[fm][fn][3] *= f1;
                }
            }
        }
#pragma unroll
        for (int s = 0; s < 8; s++) {
            uint32_t chA = (uint32_t)(((2 * s + ac) ^ swz) << 4);
            uint32_t chB = (uint32_t)(((2 * s + bc) ^ swz) << 4);
            uint32_t vh[4];
            ldm4(vh, sVt + chB);
#pragma unroll
            for (int fm = 0; fm < 2; fm++) {
                uint32_t p[4];
                ldm4(p, sSs + fm * 16 * ARSB + chA);
                mma8(acc[fm][0], p, vh[0], vh[1]);
                mma8(acc[fm][1], p, vh[2], vh[3]);
            }
        }
    }

    // epilogue: normalize and write y[b, q, h*DH + d]
    {
        const int er = lane >> 2, ec = (lane & 3) * 2;
#pragma unroll
        for (int fm = 0; fm < 2; fm++) {
            int r = mq + fm * 16 + er;
            float i0 = 1.0f / lrow[r];
            float i1 = 1.0f / lrow[r + 8];
#pragma unroll
            for (int fn = 0; fn < 2; fn++) {
                int cc = h * DH + nb + fn * 8 + ec;
                float* o0 = y + (size_t)(b * T_SEQ + q0 + r) * C_DIM + cc;
                float* o1 = y + (size_t)(b * T_SEQ + q0 + r + 8) * C_DIM + cc;
                *(float2*)o0 = make_float2(acc[fm][fn][0] * i0, acc[fm][fn][1] * i0);
                *(float2*)o1 = make_float2(acc[fm][fn][2] * i1, acc[fm][fn][3] * i1);
            }
        }
    }
}

// ---------------------------------------------------------------------------
// Launch
// ---------------------------------------------------------------------------
extern "C" void kernel_launch(void* const* d_in, const int* in_sizes, int n_in,
                              void* d_out, int out_size)
{
    const float* x      = (const float*)d_in[0];
    const float* w_qkv  = (const float*)d_in[1];
    const float* w_proj = (const float*)d_in[2];
    const float* qm     = (const float*)d_in[3];
    float* out = (float*)d_out;

    static float* p_qkv = nullptr;
    static float* p_y = nullptr;
    if (!p_qkv) {
        cudaGetSymbolAddress((void**)&p_qkv, g_qkv);
        cudaGetSymbolAddress((void**)&p_y, g_y);
        cudaFuncSetAttribute(gemm_tf32,
                             cudaFuncAttributeMaxDynamicSharedMemorySize, GEMM_SMEM);
        cudaFuncSetAttribute(attn_mma_kernel,
                             cudaFuncAttributeMaxDynamicSharedMemorySize, ATTN_SMEM);
    }

    // GEMM1: qkv = x @ w_qkv^T  (4096 x 3072 x 1024); Q,K cols need 3x-tf32
    {
        dim3 grid(C3 / 128, M_TOT / 128);
        gemm_tf32<<<grid, 256, GEMM_SMEM>>>(x, w_qkv, p_qkv, C3, C_DIM, 2 * C_DIM);
    }

    // Fused attention -> g_y
    {
        dim3 grid(T_SEQ / 64, NH, B_SZ);
        attn_mma_kernel<<<grid, 256, ATTN_SMEM>>>(qm, p_qkv, p_y);
    }

    // GEMM2: out = y @ w_proj^T  (4096 x 1024 x 1024); single tf32 is enough
    {
        dim3 grid(C_DIM / 128, M_TOT / 128);
        gemm_tf32<<<grid, 256, GEMM_SMEM>>>(p_y, w_proj, out, C_DIM, C_DIM, 0);
    }
}

// round 5
// speedup vs baseline: 1.9221x; 1.9221x over previous
#include <cuda_runtime.h>
#include <cuda_bf16.h>
#include <math.h>
#include <stdint.h>

// Problem constants
#define B_SZ   2
#define T_SEQ  2048
#define C_DIM  1024
#define C3     3072
#define NH     16
#define DH     64
#define MEMLEN 1024
#define M_TOT  4096
#define KD     1024

// Scratch (no cudaMalloc allowed)
__device__ float g_qkv[(size_t)M_TOT * C3];   // 48 MB
__device__ float g_y[(size_t)M_TOT * C_DIM];  // 16 MB
__device__ __nv_bfloat16 g_xh[(size_t)M_TOT * KD];
__device__ __nv_bfloat16 g_xl[(size_t)M_TOT * KD];
__device__ __nv_bfloat16 g_wqh[(size_t)C3 * KD];
__device__ __nv_bfloat16 g_wql[(size_t)C3 * KD];
__device__ __nv_bfloat16 g_wph[(size_t)C_DIM * KD];
__device__ __nv_bfloat16 g_wpl[(size_t)C_DIM * KD];
__device__ __nv_bfloat16 g_yh[(size_t)M_TOT * KD];
__device__ __nv_bfloat16 g_yl[(size_t)M_TOT * KD];

// ---------------------------------------------------------------------------
// helpers
// ---------------------------------------------------------------------------
__device__ __forceinline__ uint32_t pk(__nv_bfloat16 a, __nv_bfloat16 b) {
    __nv_bfloat162 t = __halves2bfloat162(a, b);
    return *reinterpret_cast<uint32_t*>(&t);
}

__device__ __forceinline__ void ldm4(uint32_t r[4], uint32_t a) {
    asm volatile("ldmatrix.sync.aligned.m8n8.x4.shared.b16 {%0,%1,%2,%3},[%4];\n"
                 : "=r"(r[0]), "=r"(r[1]), "=r"(r[2]), "=r"(r[3]) : "r"(a));
}

__device__ __forceinline__ void mma16(float d[4], const uint32_t a[4],
                                      uint32_t b0, uint32_t b1) {
    asm volatile(
        "mma.sync.aligned.m16n8k16.row.col.f32.bf16.bf16.f32 "
        "{%0,%1,%2,%3},{%4,%5,%6,%7},{%8,%9},{%0,%1,%2,%3};\n"
        : "+f"(d[0]), "+f"(d[1]), "+f"(d[2]), "+f"(d[3])
        : "r"(a[0]), "r"(a[1]), "r"(a[2]), "r"(a[3]), "r"(b0), "r"(b1));
}

__device__ __forceinline__ void cpa16(uint32_t d, const void* g) {
    asm volatile("cp.async.cg.shared.global [%0], [%1], 16;" :: "r"(d), "l"(g) : "memory");
}
__device__ __forceinline__ void cpa_commit() {
    asm volatile("cp.async.commit_group;" ::: "memory");
}
template <int N>
__device__ __forceinline__ void cpa_wait() {
    asm volatile("cp.async.wait_group %0;" :: "n"(N) : "memory");
}

// ---------------------------------------------------------------------------
// Split fp32 -> bf16 hi/lo planes (8 floats per thread)
// ---------------------------------------------------------------------------
__global__ __launch_bounds__(256)
void split_kernel(const float* __restrict__ src,
                  __nv_bfloat16* __restrict__ hi,
                  __nv_bfloat16* __restrict__ lo, int n8)
{
    int i = blockIdx.x * 256 + threadIdx.x;
    if (i >= n8) return;
    float4 v0 = ((const float4*)src)[2 * i];
    float4 v1 = ((const float4*)src)[2 * i + 1];
    float v[8] = {v0.x, v0.y, v0.z, v0.w, v1.x, v1.y, v1.z, v1.w};
    __nv_bfloat16 h[8], l[8];
#pragma unroll
    for (int j = 0; j < 8; j++) {
        h[j] = __float2bfloat16(v[j]);
        l[j] = __float2bfloat16(v[j] - __bfloat162float(h[j]));
    }
    ((uint4*)hi)[i] = make_uint4(pk(h[0],h[1]), pk(h[2],h[3]), pk(h[4],h[5]), pk(h[6],h[7]));
    ((uint4*)lo)[i] = make_uint4(pk(l[0],l[1]), pk(l[2],l[3]), pk(l[4],l[5]), pk(l[6],l[7]));
}

// ---------------------------------------------------------------------------
// bf16 3-pass NT GEMM: C[M,N](fp32) = A[M,K]*B[N,K]^T with A=Ah+Al, B=Bh+Bl.
// D = Ah*Bh + Ah*Bl + Al*Bh  (error ~2^-16)
// CTA 128x128, K-chunk 32, 3-stage cp.async pipeline, 8 warps (4Mx2N, 32x64).
// Smem plane: 128 rows x 64B, chunk swizzle: c ^= (row>>1)&3.
// ---------------------------------------------------------------------------
#define PLANE        8192
#define STAGE_BYTES  32768
#define NSTAGE       3
#define GEMM_SMEM    (NSTAGE * STAGE_BYTES)
#define NCH          32           // K / 32

__global__ __launch_bounds__(256, 2)
void gemm_bf16_kernel(const __nv_bfloat16* __restrict__ Ah,
                      const __nv_bfloat16* __restrict__ Al,
                      const __nv_bfloat16* __restrict__ Bh,
                      const __nv_bfloat16* __restrict__ Bl,
                      float* __restrict__ C, int N)
{
    extern __shared__ char smem[];
    const uint32_t sbase = (uint32_t)__cvta_generic_to_shared(smem);
    const int tid = threadIdx.x, lane = tid & 31, warp = tid >> 5;
    const int m0 = blockIdx.y * 128, n0 = blockIdx.x * 128;
    const int mw = warp >> 1, nw = warp & 1;     // 4 M-warps x 2 N-warps

    // ---- loader precompute: 8 chunks of 16B per thread per stage ----
    const __nv_bfloat16* gsrc[8];
    uint32_t sdst[8];
#pragma unroll
    for (int it = 0; it < 8; it++) {
        int c = tid + it * 256;              // 0..2047
        int p = c >> 9;                      // plane 0..3 (Ah,Al,Bh,Bl)
        int r = (c >> 2) & 127;
        int kc = c & 3;
        const __nv_bfloat16* bp = (p == 0) ? Ah : (p == 1) ? Al : (p == 2) ? Bh : Bl;
        int row = ((p < 2) ? m0 : n0) + r;
        gsrc[it] = bp + (size_t)row * KD + kc * 8;
        sdst[it] = (uint32_t)(p * PLANE + r * 64 + ((kc ^ ((r >> 1) & 3)) << 4));
    }

    // ---- fragment address precompute ----
    // A: lanes 0-15 -> rows 0-15 (k-low chunk), 16-31 -> rows 0-15 (k-high)
    const int ra = lane & 15;
    const int ksel_a = lane >> 4;
    int rowA[2], swzA[2];
#pragma unroll
    for (int f = 0; f < 2; f++) {
        rowA[f] = mw * 32 + f * 16 + ra;
        swzA[f] = (rowA[f] >> 1) & 3;
    }
    // B: lanes 0-7: n0-7 k-low; 8-15: n0-7 k-high; 16-23: n8-15 k-low; 24-31: n8-15 k-high
    const int rb = (lane & 7) + 8 * (lane >> 4);
    const int ksel_b = (lane >> 3) & 1;
    int rowB[4], swzB[4];
#pragma unroll
    for (int g = 0; g < 4; g++) {
        rowB[g] = nw * 64 + g * 16 + rb;
        swzB[g] = (rowB[g] >> 1) & 3;
    }

    float acc[2][8][4] = {};

    // ---- prologue: stages 0,1 ----
#pragma unroll
    for (int pt = 0; pt < 2; pt++) {
        uint32_t sb = sbase + pt * STAGE_BYTES;
#pragma unroll
        for (int it = 0; it < 8; it++) cpa16(sb + sdst[it], gsrc[it] + pt * 32);
        cpa_commit();
    }

    for (int t = 0; t < NCH; t++) {
        cpa_wait<1>();
        __syncthreads();

        // issue stage t+2 (overwrites buffer consumed at iter t-1; safe after barrier)
        if (t + 2 < NCH) {
            uint32_t sb = sbase + ((t + 2) % NSTAGE) * STAGE_BYTES;
#pragma unroll
            for (int it = 0; it < 8; it++) cpa16(sb + sdst[it], gsrc[it] + (t + 2) * 32);
        }
        cpa_commit();

        const uint32_t sb = sbase + (t % NSTAGE) * STAGE_BYTES;
#pragma unroll
        for (int s16 = 0; s16 < 2; s16++) {
            uint32_t ah[2][4], al[2][4];
#pragma unroll
            for (int f = 0; f < 2; f++) {
                uint32_t off = (uint32_t)(rowA[f] * 64 +
                               (((2 * s16 + ksel_a) ^ swzA[f]) << 4));
                ldm4(ah[f], sb + off);
                ldm4(al[f], sb + PLANE + off);
            }
#pragma unroll
            for (int g = 0; g < 4; g++) {
                uint32_t offb = (uint32_t)(rowB[g] * 64 +
                                (((2 * s16 + ksel_b) ^ swzB[g]) << 4));
                uint32_t bh[4], bl[4];
                ldm4(bh, sb + 2 * PLANE + offb);
                ldm4(bl, sb + 3 * PLANE + offb);
#pragma unroll
                for (int f = 0; f < 2; f++) {
#pragma unroll
                    for (int j = 0; j < 2; j++) {
                        float* d = acc[f][g * 2 + j];
                        mma16(d, ah[f], bh[2 * j], bh[2 * j + 1]);
                        mma16(d, ah[f], bl[2 * j], bl[2 * j + 1]);
                        mma16(d, al[f], bh[2 * j], bh[2 * j + 1]);
                    }
                }
            }
        }
    }

    // ---- epilogue ----
    const int er = lane >> 2, ec = (lane & 3) * 2;
#pragma unroll
    for (int f = 0; f < 2; f++) {
        int r = m0 + mw * 32 + f * 16 + er;
#pragma unroll
        for (int j8 = 0; j8 < 8; j8++) {
            int cc = n0 + nw * 64 + j8 * 8 + ec;
            *(float2*)(C + (size_t)r * N + cc) =
                make_float2(acc[f][j8][0], acc[f][j8][1]);
            *(float2*)(C + (size_t)(r + 8) * N + cc) =
                make_float2(acc[f][j8][2], acc[f][j8][3]);
        }
    }
}

// ---------------------------------------------------------------------------
// Fused flash attention (fp32 FFMA) — R2 version (known good, ~890us)
// ---------------------------------------------------------------------------
#define BQ 64
#define BKV 64
#define SPAD 65

__global__ __launch_bounds__(256)
void attn_kernel(const float* __restrict__ qm)
{
    int qt = blockIdx.x, h = blockIdx.y, b = blockIdx.z;
    int q0 = qt * BQ;
    int tid = threadIdx.x;
    int tx = tid & 15;
    int ty = tid >> 4;

    extern __shared__ float sm[];
    float* Qs = sm;
    float* Ks = Qs + BQ * SPAD;
    float* Vs = Ks + BKV * SPAD;
    float* Ss = Vs + BKV * SPAD;
    float* mrow = Ss + BQ * SPAD;
    float* lrow = mrow + BQ;
    float* frow = lrow + BQ;
    float* qscale = frow + BQ;

    if (tid < DH) qscale[tid] = logf((float)T_SEQ) * qm[tid] * rsqrtf((float)DH);
    if (tid < BQ) { mrow[tid] = -1e30f; lrow[tid] = 0.0f; }
    __syncthreads();

    const float* qbase = g_qkv + (size_t)(b * T_SEQ + q0) * C3 + h * DH;
    for (int idx = tid; idx < BQ * DH; idx += 256) {
        int r = idx >> 6, d = idx & 63;
        Qs[r * SPAD + d] = qbase[(size_t)r * C3 + d] * qscale[d];
    }
    __syncthreads();

    float acc[4][4];
#pragma unroll
    for (int i = 0; i < 4; i++)
#pragma unroll
        for (int j = 0; j < 4; j++) acc[i][j] = 0.0f;

    int maxcol = (q0 + BQ > MEMLEN) ? (q0 + BQ) : MEMLEN;
    int nTiles = maxcol / BKV;

    for (int t = 0; t < nTiles; t++) {
        int kj0 = t * BKV;
        const float* kbase = g_qkv + (size_t)(b * T_SEQ + kj0) * C3 + C_DIM + h * DH;
        const float* vbase = kbase + C_DIM;
        for (int idx = tid; idx < BKV * DH; idx += 256) {
            int r = idx >> 6, d = idx & 63;
            Ks[r * SPAD + d] = kbase[(size_t)r * C3 + d];
            Vs[r * SPAD + d] = vbase[(size_t)r * C3 + d];
        }
        __syncthreads();

        float s[4][4];
#pragma unroll
        for (int i = 0; i < 4; i++)
#pragma unroll
            for (int j = 0; j < 4; j++) s[i][j] = 0.0f;

#pragma unroll 4
        for (int d = 0; d < DH; d++) {
            float qr[4], kc[4];
#pragma unroll
            for (int i = 0; i < 4; i++) qr[i] = Qs[(ty * 4 + i) * SPAD + d];
#pragma unroll
            for (int j = 0; j < 4; j++) kc[j] = Ks[(tx * 4 + j) * SPAD + d];
#pragma unroll
            for (int i = 0; i < 4; i++)
#pragma unroll
                for (int j = 0; j < 4; j++)
                    s[i][j] = fmaf(qr[i], kc[j], s[i][j]);
        }

        bool needMask = (kj0 + BKV > MEMLEN);
#pragma unroll
        for (int i = 0; i < 4; i++) {
#pragma unroll
            for (int j = 0; j < 4; j++) {
                float v = s[i][j];
                if (needMask) {
                    int grow = q0 + ty * 4 + i;
                    int gcol = kj0 + tx * 4 + j;
                    if (gcol >= MEMLEN && gcol > grow) v = -1e30f;
                }
                Ss[(ty * 4 + i) * SPAD + tx * 4 + j] = v;
            }
        }
        __syncthreads();

        {
            int row = tid >> 2, part = tid & 3;
            float* srow = Ss + row * SPAD + part * 16;
            float mx = -1e30f;
#pragma unroll
            for (int c = 0; c < 16; c++) mx = fmaxf(mx, srow[c]);
            mx = fmaxf(mx, __shfl_xor_sync(0xffffffffu, mx, 1));
            mx = fmaxf(mx, __shfl_xor_sync(0xffffffffu, mx, 2));
            float mold = mrow[row];
            float mnew = fmaxf(mold, mx);
            float fac = __expf(mold - mnew);
            float lsum = 0.0f;
#pragma unroll
            for (int c = 0; c < 16; c++) {
                float p = __expf(srow[c] - mnew);
                srow[c] = p;
                lsum += p;
            }
            lsum += __shfl_xor_sync(0xffffffffu, lsum, 1);
            lsum += __shfl_xor_sync(0xffffffffu, lsum, 2);
            if (part == 0) {
                mrow[row] = mnew;
                lrow[row] = lrow[row] * fac + lsum;
                frow[row] = fac;
            }
        }
        __syncthreads();

        float fi[4];
#pragma unroll
        for (int i = 0; i < 4; i++) fi[i] = frow[ty * 4 + i];
#pragma unroll
        for (int i = 0; i < 4; i++)
#pragma unroll
            for (int j = 0; j < 4; j++) acc[i][j] *= fi[i];

#pragma unroll 4
        for (int kk = 0; kk < BKV; kk++) {
            float pv[4], vv[4];
#pragma unroll
            for (int i = 0; i < 4; i++) pv[i] = Ss[(ty * 4 + i) * SPAD + kk];
#pragma unroll
            for (int j = 0; j < 4; j++) vv[j] = Vs[kk * SPAD + tx * 4 + j];
#pragma unroll
            for (int i = 0; i < 4; i++)
#pragma unroll
                for (int j = 0; j < 4; j++)
                    acc[i][j] = fmaf(pv[i], vv[j], acc[i][j]);
        }
        __syncthreads();
    }

#pragma unroll
    for (int i = 0; i < 4; i++) {
        float inv = 1.0f / lrow[ty * 4 + i];
        float* yrow = g_y + (size_t)(b * T_SEQ + q0 + ty * 4 + i) * C_DIM + h * DH + tx * 4;
#pragma unroll
        for (int j = 0; j < 4; j++) yrow[j] = acc[i][j] * inv;
    }
}

// ---------------------------------------------------------------------------
// Launch
// ---------------------------------------------------------------------------
static const int ATTN_SMEM =
    (BQ * SPAD + BKV * SPAD + BKV * SPAD + BQ * SPAD + 3 * BQ + DH) * (int)sizeof(float);

extern "C" void kernel_launch(void* const* d_in, const int* in_sizes, int n_in,
                              void* d_out, int out_size)
{
    const float* x      = (const float*)d_in[0];
    const float* w_qkv  = (const float*)d_in[1];
    const float* w_proj = (const float*)d_in[2];
    const float* qm     = (const float*)d_in[3];
    float* out = (float*)d_out;

    static float *p_qkv = nullptr, *p_y = nullptr;
    static __nv_bfloat16 *p_xh, *p_xl, *p_wqh, *p_wql, *p_wph, *p_wpl, *p_yh, *p_yl;
    if (!p_qkv) {
        cudaGetSymbolAddress((void**)&p_qkv, g_qkv);
        cudaGetSymbolAddress((void**)&p_y, g_y);
        cudaGetSymbolAddress((void**)&p_xh, g_xh);
        cudaGetSymbolAddress((void**)&p_xl, g_xl);
        cudaGetSymbolAddress((void**)&p_wqh, g_wqh);
        cudaGetSymbolAddress((void**)&p_wql, g_wql);
        cudaGetSymbolAddress((void**)&p_wph, g_wph);
        cudaGetSymbolAddress((void**)&p_wpl, g_wpl);
        cudaGetSymbolAddress((void**)&p_yh, g_yh);
        cudaGetSymbolAddress((void**)&p_yl, g_yl);
        cudaFuncSetAttribute(gemm_bf16_kernel,
                             cudaFuncAttributeMaxDynamicSharedMemorySize, GEMM_SMEM);
        cudaFuncSetAttribute(attn_kernel,
                             cudaFuncAttributeMaxDynamicSharedMemorySize, ATTN_SMEM);
    }

    // Pre-split inputs to bf16 hi/lo planes
    split_kernel<<<(M_TOT * KD / 8 + 255) / 256, 256>>>(x, p_xh, p_xl, M_TOT * KD / 8);
    split_kernel<<<(C3 * KD / 8 + 255) / 256, 256>>>(w_qkv, p_wqh, p_wql, C3 * KD / 8);
    split_kernel<<<(C_DIM * KD / 8 + 255) / 256, 256>>>(w_proj, p_wph, p_wpl, C_DIM * KD / 8);

    // GEMM1: qkv = x @ w_qkv^T  (4096 x 3072 x 1024)
    {
        dim3 grid(C3 / 128, M_TOT / 128);
        gemm_bf16_kernel<<<grid, 256, GEMM_SMEM>>>(p_xh, p_xl, p_wqh, p_wql, p_qkv, C3);
    }

    // Fused attention -> g_y
    {
        dim3 grid(T_SEQ / BQ, NH, B_SZ);
        attn_kernel<<<grid, 256, ATTN_SMEM>>>(qm);
    }

    // Split attention output, then GEMM2: out = y @ w_proj^T
    split_kernel<<<(M_TOT * KD / 8 + 255) / 256, 256>>>(p_y, p_yh, p_yl, M_TOT * KD / 8);
    {
        dim3 grid(C_DIM / 128, M_TOT / 128);
        gemm_bf16_kernel<<<grid, 256, GEMM_SMEM>>>(p_yh, p_yl, p_wph, p_wpl, out, C_DIM);
    }
}

// round 6
// speedup vs baseline: 4.2785x; 2.2259x over previous
#include <cuda_runtime.h>
#include <cuda_bf16.h>
#include <math.h>
#include <stdint.h>

// Problem constants
#define B_SZ   2
#define T_SEQ  2048
#define C_DIM  1024
#define C3     3072
#define NH     16
#define DH     64
#define MEMLEN 1024
#define M_TOT  4096
#define KD     1024

// Scratch bf16 hi/lo planes (no cudaMalloc allowed)
__device__ __nv_bfloat16 g_xh[(size_t)M_TOT * KD];
__device__ __nv_bfloat16 g_xl[(size_t)M_TOT * KD];
__device__ __nv_bfloat16 g_wqh[(size_t)C3 * KD];
__device__ __nv_bfloat16 g_wql[(size_t)C3 * KD];
__device__ __nv_bfloat16 g_wph[(size_t)C_DIM * KD];
__device__ __nv_bfloat16 g_wpl[(size_t)C_DIM * KD];
__device__ __nv_bfloat16 g_qkvh[(size_t)M_TOT * C3];
__device__ __nv_bfloat16 g_qkvl[(size_t)M_TOT * C3];
__device__ __nv_bfloat16 g_yh[(size_t)M_TOT * KD];
__device__ __nv_bfloat16 g_yl[(size_t)M_TOT * KD];

// ---------------------------------------------------------------------------
// helpers
// ---------------------------------------------------------------------------
__device__ __forceinline__ uint32_t pk(__nv_bfloat16 a, __nv_bfloat16 b) {
    __nv_bfloat162 t = __halves2bfloat162(a, b);
    return *reinterpret_cast<uint32_t*>(&t);
}

__device__ __forceinline__ uint32_t pkf(float a, float b, uint32_t* lo) {
    __nv_bfloat16 ha = __float2bfloat16(a), hb = __float2bfloat16(b);
    __nv_bfloat16 la = __float2bfloat16(a - __bfloat162float(ha));
    __nv_bfloat16 lb = __float2bfloat16(b - __bfloat162float(hb));
    *lo = pk(la, lb);
    return pk(ha, hb);
}

__device__ __forceinline__ void ldm4(uint32_t r[4], uint32_t a) {
    asm volatile("ldmatrix.sync.aligned.m8n8.x4.shared.b16 {%0,%1,%2,%3},[%4];\n"
                 : "=r"(r[0]), "=r"(r[1]), "=r"(r[2]), "=r"(r[3]) : "r"(a));
}
__device__ __forceinline__ void ldm4t(uint32_t r[4], uint32_t a) {
    asm volatile("ldmatrix.sync.aligned.m8n8.x4.trans.shared.b16 {%0,%1,%2,%3},[%4];\n"
                 : "=r"(r[0]), "=r"(r[1]), "=r"(r[2]), "=r"(r[3]) : "r"(a));
}

__device__ __forceinline__ void mma16(float d[4], const uint32_t a[4],
                                      uint32_t b0, uint32_t b1) {
    asm volatile(
        "mma.sync.aligned.m16n8k16.row.col.f32.bf16.bf16.f32 "
        "{%0,%1,%2,%3},{%4,%5,%6,%7},{%8,%9},{%0,%1,%2,%3};\n"
        : "+f"(d[0]), "+f"(d[1]), "+f"(d[2]), "+f"(d[3])
        : "r"(a[0]), "r"(a[1]), "r"(a[2]), "r"(a[3]), "r"(b0), "r"(b1));
}

__device__ __forceinline__ void cpa16(uint32_t d, const void* g) {
    asm volatile("cp.async.cg.shared.global [%0], [%1], 16;" :: "r"(d), "l"(g) : "memory");
}
__device__ __forceinline__ void cpa_commit() {
    asm volatile("cp.async.commit_group;" ::: "memory");
}
template <int N>
__device__ __forceinline__ void cpa_wait() {
    asm volatile("cp.async.wait_group %0;" :: "n"(N) : "memory");
}

// ---------------------------------------------------------------------------
// Split fp32 -> bf16 hi/lo planes
// ---------------------------------------------------------------------------
__global__ __launch_bounds__(256)
void split_kernel(const float* __restrict__ src,
                  __nv_bfloat16* __restrict__ hi,
                  __nv_bfloat16* __restrict__ lo, int n8)
{
    int i = blockIdx.x * 256 + threadIdx.x;
    if (i >= n8) return;
    float4 v0 = ((const float4*)src)[2 * i];
    float4 v1 = ((const float4*)src)[2 * i + 1];
    float v[8] = {v0.x, v0.y, v0.z, v0.w, v1.x, v1.y, v1.z, v1.w};
    __nv_bfloat16 h[8], l[8];
#pragma unroll
    for (int j = 0; j < 8; j++) {
        h[j] = __float2bfloat16(v[j]);
        l[j] = __float2bfloat16(v[j] - __bfloat162float(h[j]));
    }
    ((uint4*)hi)[i] = make_uint4(pk(h[0],h[1]), pk(h[2],h[3]), pk(h[4],h[5]), pk(h[6],h[7]));
    ((uint4*)lo)[i] = make_uint4(pk(l[0],l[1]), pk(l[2],l[3]), pk(l[4],l[5]), pk(l[6],l[7]));
}

// ---------------------------------------------------------------------------
// bf16 3-pass NT GEMM (R5). Optionally writes bf16 hi/lo planes instead of fp32.
// ---------------------------------------------------------------------------
#define PLANE        8192
#define STAGE_BYTES  32768
#define NSTAGE       3
#define GEMM_SMEM    (NSTAGE * STAGE_BYTES)
#define NCH          32

__global__ __launch_bounds__(256, 2)
void gemm_bf16_kernel(const __nv_bfloat16* __restrict__ Ah,
                      const __nv_bfloat16* __restrict__ Al,
                      const __nv_bfloat16* __restrict__ Bh,
                      const __nv_bfloat16* __restrict__ Bl,
                      float* __restrict__ C,
                      __nv_bfloat16* __restrict__ Ch,
                      __nv_bfloat16* __restrict__ Cl, int N)
{
    extern __shared__ char smem[];
    const uint32_t sbase = (uint32_t)__cvta_generic_to_shared(smem);
    const int tid = threadIdx.x, lane = tid & 31, warp = tid >> 5;
    const int m0 = blockIdx.y * 128, n0 = blockIdx.x * 128;
    const int mw = warp >> 1, nw = warp & 1;

    const __nv_bfloat16* gsrc[8];
    uint32_t sdst[8];
#pragma unroll
    for (int it = 0; it < 8; it++) {
        int c = tid + it * 256;
        int p = c >> 9;
        int r = (c >> 2) & 127;
        int kc = c & 3;
        const __nv_bfloat16* bp = (p == 0) ? Ah : (p == 1) ? Al : (p == 2) ? Bh : Bl;
        int row = ((p < 2) ? m0 : n0) + r;
        gsrc[it] = bp + (size_t)row * KD + kc * 8;
        sdst[it] = (uint32_t)(p * PLANE + r * 64 + ((kc ^ ((r >> 1) & 3)) << 4));
    }

    const int ra = lane & 15;
    const int ksel_a = lane >> 4;
    int rowA[2], swzA[2];
#pragma unroll
    for (int f = 0; f < 2; f++) {
        rowA[f] = mw * 32 + f * 16 + ra;
        swzA[f] = (rowA[f] >> 1) & 3;
    }
    const int rb = (lane & 7) + 8 * (lane >> 4);
    const int ksel_b = (lane >> 3) & 1;
    int rowB[4], swzB[4];
#pragma unroll
    for (int g = 0; g < 4; g++) {
        rowB[g] = nw * 64 + g * 16 + rb;
        swzB[g] = (rowB[g] >> 1) & 3;
    }

    float acc[2][8][4] = {};

#pragma unroll
    for (int pt = 0; pt < 2; pt++) {
        uint32_t sb = sbase + pt * STAGE_BYTES;
#pragma unroll
        for (int it = 0; it < 8; it++) cpa16(sb + sdst[it], gsrc[it] + pt * 32);
        cpa_commit();
    }

    for (int t = 0; t < NCH; t++) {
        cpa_wait<1>();
        __syncthreads();

        if (t + 2 < NCH) {
            uint32_t sb = sbase + ((t + 2) % NSTAGE) * STAGE_BYTES;
#pragma unroll
            for (int it = 0; it < 8; it++) cpa16(sb + sdst[it], gsrc[it] + (t + 2) * 32);
        }
        cpa_commit();

        const uint32_t sb = sbase + (t % NSTAGE) * STAGE_BYTES;
#pragma unroll
        for (int s16 = 0; s16 < 2; s16++) {
            uint32_t ah[2][4], al[2][4];
#pragma unroll
            for (int f = 0; f < 2; f++) {
                uint32_t off = (uint32_t)(rowA[f] * 64 +
                               (((2 * s16 + ksel_a) ^ swzA[f]) << 4));
                ldm4(ah[f], sb + off);
                ldm4(al[f], sb + PLANE + off);
            }
#pragma unroll
            for (int g = 0; g < 4; g++) {
                uint32_t offb = (uint32_t)(rowB[g] * 64 +
                                (((2 * s16 + ksel_b) ^ swzB[g]) << 4));
                uint32_t bh[4], bl[4];
                ldm4(bh, sb + 2 * PLANE + offb);
                ldm4(bl, sb + 3 * PLANE + offb);
#pragma unroll
                for (int f = 0; f < 2; f++) {
#pragma unroll
                    for (int j = 0; j < 2; j++) {
                        float* d = acc[f][g * 2 + j];
                        mma16(d, ah[f], bh[2 * j], bh[2 * j + 1]);
                        mma16(d, ah[f], bl[2 * j], bl[2 * j + 1]);
                        mma16(d, al[f], bh[2 * j], bh[2 * j + 1]);
                    }
                }
            }
        }
    }

    const int er = lane >> 2, ec = (lane & 3) * 2;
#pragma unroll
    for (int f = 0; f < 2; f++) {
        int r = m0 + mw * 32 + f * 16 + er;
#pragma unroll
        for (int j8 = 0; j8 < 8; j8++) {
            int cc = n0 + nw * 64 + j8 * 8 + ec;
            if (Ch) {
                uint32_t lo0, lo1;
                uint32_t hi0 = pkf(acc[f][j8][0], acc[f][j8][1], &lo0);
                uint32_t hi1 = pkf(acc[f][j8][2], acc[f][j8][3], &lo1);
                *(uint32_t*)(Ch + (size_t)r * N + cc) = hi0;
                *(uint32_t*)(Cl + (size_t)r * N + cc) = lo0;
                *(uint32_t*)(Ch + (size_t)(r + 8) * N + cc) = hi1;
                *(uint32_t*)(Cl + (size_t)(r + 8) * N + cc) = lo1;
            } else {
                *(float2*)(C + (size_t)r * N + cc) =
                    make_float2(acc[f][j8][0], acc[f][j8][1]);
                *(float2*)(C + (size_t)(r + 8) * N + cc) =
                    make_float2(acc[f][j8][2], acc[f][j8][3]);
            }
        }
    }
}

// ---------------------------------------------------------------------------
// bf16 mma flash attention.
// CTA = (128 q-rows, head, batch), 256 thr, 8 warps (16 q-rows each).
// S = QK^T 3-pass hi/lo; P kept in registers (C-frag == A-frag trick);
// P@V 3-pass with V^T via ldmatrix.trans. KV double-buffered cp.async.
// All tiles: rows of 128B (64 bf16), chunk swizzle ch ^= row&7.
// ---------------------------------------------------------------------------
#define AQ 128
#define AKV 64
#define QH_OFF   0
#define QL_OFF   16384
#define ST_OFF   32768
#define AST      32768     // per-stage bytes: Kh,Kl,Vh,Vl @ +0,8192,16384,24576
#define QSC_OFF  (ST_OFF + 2 * AST)
#define ATTN2_SMEM (QSC_OFF + 256)

__global__ __launch_bounds__(256)
void attn_mma2(const float* __restrict__ qm,
               const __nv_bfloat16* __restrict__ qkvh,
               const __nv_bfloat16* __restrict__ qkvl,
               __nv_bfloat16* __restrict__ yh,
               __nv_bfloat16* __restrict__ yl)
{
    extern __shared__ char smem[];
    const uint32_t sb = (uint32_t)__cvta_generic_to_shared(smem);
    float* qsc = (float*)(smem + QSC_OFF);
    const int tid = threadIdx.x, lane = tid & 31, warp = tid >> 5;
    const int qt = blockIdx.x, h = blockIdx.y, b = blockIdx.z;
    const int q0 = qt * AQ;

    if (tid < 64) qsc[tid] = logf(2048.0f) * qm[tid] * rsqrtf(64.0f);

    // ---- KV loader precompute (8 x 16B per thread per stage) ----
    const __nv_bfloat16* kvsrc[8];
    uint32_t kvdst[8];
#pragma unroll
    for (int it = 0; it < 8; it++) {
        int c = tid + it * 256;
        int p = c >> 9, r = (c >> 3) & 63, ch = c & 7;
        const __nv_bfloat16* bp = (p & 1) ? qkvl : qkvh;
        int col = ((p >> 1) ? 2 * C_DIM : C_DIM) + h * DH + ch * 8;
        kvsrc[it] = bp + (size_t)(b * T_SEQ + r) * C3 + col;
        kvdst[it] = (uint32_t)(p * 8192 + r * 128 + ((ch ^ (r & 7)) << 4));
    }
    // issue stage 0 (tile 0)
#pragma unroll
    for (int it = 0; it < 8; it++) cpa16(sb + ST_OFF + kvdst[it], kvsrc[it]);
    cpa_commit();

    __syncthreads();   // qsc visible

    // ---- load Q: combine hi+lo, scale, re-split, store smem ----
#pragma unroll
    for (int it = 0; it < 4; it++) {
        int u = tid + it * 256;
        int r = u >> 3, ch = u & 7;
        size_t src = (size_t)(b * T_SEQ + q0 + r) * C3 + h * DH + ch * 8;
        uint4 hv = *(const uint4*)(qkvh + src);
        uint4 lv = *(const uint4*)(qkvl + src);
        const __nv_bfloat162* hp = (const __nv_bfloat162*)&hv;
        const __nv_bfloat162* lp = (const __nv_bfloat162*)&lv;
        uint32_t oh[4], ol[4];
#pragma unroll
        for (int k = 0; k < 4; k++) {
            float2 hf = __bfloat1622float2(hp[k]);
            float2 lf = __bfloat1622float2(lp[k]);
            float v0 = (hf.x + lf.x) * qsc[ch * 8 + 2 * k];
            float v1 = (hf.y + lf.y) * qsc[ch * 8 + 2 * k + 1];
            oh[k] = pkf(v0, v1, &ol[k]);
        }
        uint32_t off = (uint32_t)(r * 128 + ((ch ^ (r & 7)) << 4));
        *(uint4*)(smem + QH_OFF + off) = make_uint4(oh[0], oh[1], oh[2], oh[3]);
        *(uint4*)(smem + QL_OFF + off) = make_uint4(ol[0], ol[1], ol[2], ol[3]);
    }

    float m0 = -1e30f, m1 = -1e30f, l0 = 0.0f, l1 = 0.0f;
    float acc[8][4] = {};

    const int maxc = (q0 + AQ > MEMLEN) ? (q0 + AQ) : MEMLEN;
    const int nT = maxc / AKV;

    for (int t = 0; t < nT; t++) {
        cpa_wait<0>();
        __syncthreads();
        if (t + 1 < nT) {
            uint32_t stb = sb + ST_OFF + ((t + 1) & 1) * AST;
            size_t delta = (size_t)(t + 1) * AKV * C3;
#pragma unroll
            for (int it = 0; it < 8; it++) cpa16(stb + kvdst[it], kvsrc[it] + delta);
            cpa_commit();
        }
        const uint32_t st = sb + ST_OFF + (t & 1) * AST;

        // ---- S = Q K^T (3-pass) ----
        float s_[8][4] = {};
#pragma unroll
        for (int kk = 0; kk < 4; kk++) {
            uint32_t aH[4], aL[4];
            {
                int row = 16 * warp + (lane & 15);
                int ch = kk * 2 + (lane >> 4);
                uint32_t off = (uint32_t)(row * 128 + ((ch ^ (row & 7)) << 4));
                ldm4(aH, sb + QH_OFF + off);
                ldm4(aL, sb + QL_OFF + off);
            }
#pragma unroll
            for (int jj = 0; jj < 4; jj++) {
                int row = 16 * jj + 8 * (lane >> 4) + (lane & 7);
                int ch = kk * 2 + ((lane >> 3) & 1);
                uint32_t off = (uint32_t)(row * 128 + ((ch ^ (row & 7)) << 4));
                uint32_t bH[4], bL[4];
                ldm4(bH, st + off);
                ldm4(bL, st + 8192 + off);
#pragma unroll
                for (int u = 0; u < 2; u++) {
                    float* d = s_[2 * jj + u];
                    mma16(d, aH, bH[2 * u], bH[2 * u + 1]);
                    mma16(d, aH, bL[2 * u], bL[2 * u + 1]);
                    mma16(d, aL, bH[2 * u], bH[2 * u + 1]);
                }
            }
        }

        // ---- mask ----
        const int kj0 = t * AKV;
        if (kj0 >= MEMLEN) {
            int r0g = q0 + 16 * warp + (lane >> 2);
            int cb = kj0 + 2 * (lane & 3);
#pragma unroll
            for (int j = 0; j < 8; j++) {
                int cg = cb + 8 * j;
                if (cg > r0g)         s_[j][0] = -1e30f;
                if (cg + 1 > r0g)     s_[j][1] = -1e30f;
                if (cg > r0g + 8)     s_[j][2] = -1e30f;
                if (cg + 1 > r0g + 8) s_[j][3] = -1e30f;
            }
        }

        // ---- online softmax (quad = one row pair) ----
        float mx0 = -1e30f, mx1 = -1e30f;
#pragma unroll
        for (int j = 0; j < 8; j++) {
            mx0 = fmaxf(mx0, fmaxf(s_[j][0], s_[j][1]));
            mx1 = fmaxf(mx1, fmaxf(s_[j][2], s_[j][3]));
        }
        mx0 = fmaxf(mx0, __shfl_xor_sync(0xffffffffu, mx0, 1));
        mx0 = fmaxf(mx0, __shfl_xor_sync(0xffffffffu, mx0, 2));
        mx1 = fmaxf(mx1, __shfl_xor_sync(0xffffffffu, mx1, 1));
        mx1 = fmaxf(mx1, __shfl_xor_sync(0xffffffffu, mx1, 2));
        float mn0 = fmaxf(m0, mx0), mn1 = fmaxf(m1, mx1);
        float f0 = __expf(m0 - mn0), f1 = __expf(m1 - mn1);
        float sum0 = 0.0f, sum1 = 0.0f;
        uint32_t phA[8], phB[8], plA[8], plB[8];
#pragma unroll
        for (int j = 0; j < 8; j++) {
            float p0 = __expf(s_[j][0] - mn0);
            float p1 = __expf(s_[j][1] - mn0);
            float p2 = __expf(s_[j][2] - mn1);
            float p3 = __expf(s_[j][3] - mn1);
            sum0 += p0 + p1; sum1 += p2 + p3;
            phA[j] = pkf(p0, p1, &plA[j]);
            phB[j] = pkf(p2, p3, &plB[j]);
        }
        sum0 += __shfl_xor_sync(0xffffffffu, sum0, 1);
        sum0 += __shfl_xor_sync(0xffffffffu, sum0, 2);
        sum1 += __shfl_xor_sync(0xffffffffu, sum1, 1);
        sum1 += __shfl_xor_sync(0xffffffffu, sum1, 2);
        l0 = l0 * f0 + sum0; l1 = l1 * f1 + sum1;
        m0 = mn0; m1 = mn1;
#pragma unroll
        for (int j = 0; j < 8; j++) {
            acc[j][0] *= f0; acc[j][1] *= f0;
            acc[j][2] *= f1; acc[j][3] *= f1;
        }

        // ---- P @ V (3-pass), V^T via ldmatrix.trans ----
#pragma unroll
        for (int jj = 0; jj < 4; jj++) {
            uint32_t pa[4] = {phA[2*jj], phB[2*jj], phA[2*jj+1], phB[2*jj+1]};
            uint32_t pb[4] = {plA[2*jj], plB[2*jj], plA[2*jj+1], plB[2*jj+1]};
#pragma unroll
            for (int nn = 0; nn < 4; nn++) {
                int row = 16 * jj + 8 * ((lane >> 3) & 1) + (lane & 7);
                int ch = 2 * nn + (lane >> 4);
                uint32_t off = (uint32_t)(row * 128 + ((ch ^ (row & 7)) << 4));
                uint32_t vH[4], vL[4];
                ldm4t(vH, st + 16384 + off);
                ldm4t(vL, st + 24576 + off);
#pragma unroll
                for (int u = 0; u < 2; u++) {
                    float* d = acc[2 * nn + u];
                    mma16(d, pa, vH[2 * u], vH[2 * u + 1]);
                    mma16(d, pa, vL[2 * u], vL[2 * u + 1]);
                    mma16(d, pb, vH[2 * u], vH[2 * u + 1]);
                }
            }
        }
    }

    // ---- epilogue: normalize, split, write y hi/lo planes ----
    {
        float i0 = 1.0f / l0, i1 = 1.0f / l1;
        size_t r0 = (size_t)(b * T_SEQ + q0 + 16 * warp + (lane >> 2));
        int cb = h * DH + 2 * (lane & 3);
#pragma unroll
        for (int j = 0; j < 8; j++) {
            int cc = cb + 8 * j;
            uint32_t lo0, lo1;
            uint32_t hi0 = pkf(acc[j][0] * i0, acc[j][1] * i0, &lo0);
            uint32_t hi1 = pkf(acc[j][2] * i1, acc[j][3] * i1, &lo1);
            *(uint32_t*)(yh + r0 * C_DIM + cc) = hi0;
            *(uint32_t*)(yl + r0 * C_DIM + cc) = lo0;
            *(uint32_t*)(yh + (r0 + 8) * C_DIM + cc) = hi1;
            *(uint32_t*)(yl + (r0 + 8) * C_DIM + cc) = lo1;
        }
    }
}

// ---------------------------------------------------------------------------
// Launch
// ---------------------------------------------------------------------------
extern "C" void kernel_launch(void* const* d_in, const int* in_sizes, int n_in,
                              void* d_out, int out_size)
{
    const float* x      = (const float*)d_in[0];
    const float* w_qkv  = (const float*)d_in[1];
    const float* w_proj = (const float*)d_in[2];
    const float* qm     = (const float*)d_in[3];
    float* out = (float*)d_out;

    static __nv_bfloat16 *p_xh = nullptr, *p_xl, *p_wqh, *p_wql, *p_wph, *p_wpl;
    static __nv_bfloat16 *p_qkvh, *p_qkvl, *p_yh, *p_yl;
    if (!p_xh) {
        cudaGetSymbolAddress((void**)&p_xh, g_xh);
        cudaGetSymbolAddress((void**)&p_xl, g_xl);
        cudaGetSymbolAddress((void**)&p_wqh, g_wqh);
        cudaGetSymbolAddress((void**)&p_wql, g_wql);
        cudaGetSymbolAddress((void**)&p_wph, g_wph);
        cudaGetSymbolAddress((void**)&p_wpl, g_wpl);
        cudaGetSymbolAddress((void**)&p_qkvh, g_qkvh);
        cudaGetSymbolAddress((void**)&p_qkvl, g_qkvl);
        cudaGetSymbolAddress((void**)&p_yh, g_yh);
        cudaGetSymbolAddress((void**)&p_yl, g_yl);
        cudaFuncSetAttribute(gemm_bf16_kernel,
                             cudaFuncAttributeMaxDynamicSharedMemorySize, GEMM_SMEM);
        cudaFuncSetAttribute(attn_mma2,
                             cudaFuncAttributeMaxDynamicSharedMemorySize, ATTN2_SMEM);
    }

    // Split fp32 inputs into bf16 hi/lo planes
    split_kernel<<<(M_TOT * KD / 8 + 255) / 256, 256>>>(x, p_xh, p_xl, M_TOT * KD / 8);
    split_kernel<<<(C3 * KD / 8 + 255) / 256, 256>>>(w_qkv, p_wqh, p_wql, C3 * KD / 8);
    split_kernel<<<(C_DIM * KD / 8 + 255) / 256, 256>>>(w_proj, p_wph, p_wpl, C_DIM * KD / 8);

    // GEMM1: qkv = x @ w_qkv^T -> bf16 hi/lo planes
    {
        dim3 grid(C3 / 128, M_TOT / 128);
        gemm_bf16_kernel<<<grid, 256, GEMM_SMEM>>>(p_xh, p_xl, p_wqh, p_wql,
                                                   nullptr, p_qkvh, p_qkvl, C3);
    }

    // Fused attention -> y hi/lo planes
    {
        dim3 grid(T_SEQ / AQ, NH, B_SZ);
        attn_mma2<<<grid, 256, ATTN2_SMEM>>>(qm, p_qkvh, p_qkvl, p_yh, p_yl);
    }

    // GEMM2: out = y @ w_proj^T -> fp32
    {
        dim3 grid(C_DIM / 128, M_TOT / 128);
        gemm_bf16_kernel<<<grid, 256, GEMM_SMEM>>>(p_yh, p_yl, p_wph, p_wpl,
                                                   out, nullptr, nullptr, C_DIM);
    }
}

// round 7
// speedup vs baseline: 4.2953x; 1.0039x over previous
#include <cuda_runtime.h>
#include <cuda_bf16.h>
#include <math.h>
#include <stdint.h>

// Problem constants
#define B_SZ   2
#define T_SEQ  2048
#define C_DIM  1024
#define C3     3072
#define NH     16
#define DH     64
#define MEMLEN 1024
#define M_TOT  4096
#define KD     1024

// Scratch bf16 hi/lo planes (no cudaMalloc allowed)
__device__ __nv_bfloat16 g_xh[(size_t)M_TOT * KD];
__device__ __nv_bfloat16 g_xl[(size_t)M_TOT * KD];
__device__ __nv_bfloat16 g_wqh[(size_t)C3 * KD];
__device__ __nv_bfloat16 g_wql[(size_t)C3 * KD];
__device__ __nv_bfloat16 g_wph[(size_t)C_DIM * KD];
__device__ __nv_bfloat16 g_wpl[(size_t)C_DIM * KD];
__device__ __nv_bfloat16 g_qkvh[(size_t)M_TOT * C3];
__device__ __nv_bfloat16 g_qkvl[(size_t)M_TOT * C3];
__device__ __nv_bfloat16 g_yh[(size_t)M_TOT * KD];
__device__ __nv_bfloat16 g_yl[(size_t)M_TOT * KD];

// ---------------------------------------------------------------------------
// helpers
// ---------------------------------------------------------------------------
__device__ __forceinline__ uint32_t pk(__nv_bfloat16 a, __nv_bfloat16 b) {
    __nv_bfloat162 t = __halves2bfloat162(a, b);
    return *reinterpret_cast<uint32_t*>(&t);
}

__device__ __forceinline__ uint32_t pkf(float a, float b, uint32_t* lo) {
    __nv_bfloat16 ha = __float2bfloat16(a), hb = __float2bfloat16(b);
    __nv_bfloat16 la = __float2bfloat16(a - __bfloat162float(ha));
    __nv_bfloat16 lb = __float2bfloat16(b - __bfloat162float(hb));
    *lo = pk(la, lb);
    return pk(ha, hb);
}

__device__ __forceinline__ void ldm4(uint32_t r[4], uint32_t a) {
    asm volatile("ldmatrix.sync.aligned.m8n8.x4.shared.b16 {%0,%1,%2,%3},[%4];\n"
                 : "=r"(r[0]), "=r"(r[1]), "=r"(r[2]), "=r"(r[3]) : "r"(a));
}
__device__ __forceinline__ void ldm4t(uint32_t r[4], uint32_t a) {
    asm volatile("ldmatrix.sync.aligned.m8n8.x4.trans.shared.b16 {%0,%1,%2,%3},[%4];\n"
                 : "=r"(r[0]), "=r"(r[1]), "=r"(r[2]), "=r"(r[3]) : "r"(a));
}

__device__ __forceinline__ void mma16(float d[4], const uint32_t a[4],
                                      uint32_t b0, uint32_t b1) {
    asm volatile(
        "mma.sync.aligned.m16n8k16.row.col.f32.bf16.bf16.f32 "
        "{%0,%1,%2,%3},{%4,%5,%6,%7},{%8,%9},{%0,%1,%2,%3};\n"
        : "+f"(d[0]), "+f"(d[1]), "+f"(d[2]), "+f"(d[3])
        : "r"(a[0]), "r"(a[1]), "r"(a[2]), "r"(a[3]), "r"(b0), "r"(b1));
}

__device__ __forceinline__ void cpa16(uint32_t d, const void* g) {
    asm volatile("cp.async.cg.shared.global [%0], [%1], 16;" :: "r"(d), "l"(g) : "memory");
}
__device__ __forceinline__ void cpa_commit() {
    asm volatile("cp.async.commit_group;" ::: "memory");
}
template <int N>
__device__ __forceinline__ void cpa_wait() {
    asm volatile("cp.async.wait_group %0;" :: "n"(N) : "memory");
}

// ---------------------------------------------------------------------------
// Split fp32 -> bf16 hi/lo planes
// ---------------------------------------------------------------------------
__global__ __launch_bounds__(256)
void split_kernel(const float* __restrict__ src,
                  __nv_bfloat16* __restrict__ hi,
                  __nv_bfloat16* __restrict__ lo, int n8)
{
    int i = blockIdx.x * 256 + threadIdx.x;
    if (i >= n8) return;
    float4 v0 = ((const float4*)src)[2 * i];
    float4 v1 = ((const float4*)src)[2 * i + 1];
    float v[8] = {v0.x, v0.y, v0.z, v0.w, v1.x, v1.y, v1.z, v1.w};
    __nv_bfloat16 h[8], l[8];
#pragma unroll
    for (int j = 0; j < 8; j++) {
        h[j] = __float2bfloat16(v[j]);
        l[j] = __float2bfloat16(v[j] - __bfloat162float(h[j]));
    }
    ((uint4*)hi)[i] = make_uint4(pk(h[0],h[1]), pk(h[2],h[3]), pk(h[4],h[5]), pk(h[6],h[7]));
    ((uint4*)lo)[i] = make_uint4(pk(l[0],l[1]), pk(l[2],l[3]), pk(l[4],l[5]), pk(l[6],l[7]));
}

// ---------------------------------------------------------------------------
// bf16 3-pass NT GEMM. Pass-interleaved mma order (same-acc distance 4).
// ---------------------------------------------------------------------------
#define PLANE        8192
#define STAGE_BYTES  32768
#define NSTAGE       3
#define GEMM_SMEM    (NSTAGE * STAGE_BYTES)
#define NCH          32

__global__ __launch_bounds__(256, 2)
void gemm_bf16_kernel(const __nv_bfloat16* __restrict__ Ah,
                      const __nv_bfloat16* __restrict__ Al,
                      const __nv_bfloat16* __restrict__ Bh,
                      const __nv_bfloat16* __restrict__ Bl,
                      float* __restrict__ C,
                      __nv_bfloat16* __restrict__ Ch,
                      __nv_bfloat16* __restrict__ Cl, int N)
{
    extern __shared__ char smem[];
    const uint32_t sbase = (uint32_t)__cvta_generic_to_shared(smem);
    const int tid = threadIdx.x, lane = tid & 31, warp = tid >> 5;
    const int m0 = blockIdx.y * 128, n0 = blockIdx.x * 128;
    const int mw = warp >> 1, nw = warp & 1;

    const __nv_bfloat16* gsrc[8];
    uint32_t sdst[8];
#pragma unroll
    for (int it = 0; it < 8; it++) {
        int c = tid + it * 256;
        int p = c >> 9;
        int r = (c >> 2) & 127;
        int kc = c & 3;
        const __nv_bfloat16* bp = (p == 0) ? Ah : (p == 1) ? Al : (p == 2) ? Bh : Bl;
        int row = ((p < 2) ? m0 : n0) + r;
        gsrc[it] = bp + (size_t)row * KD + kc * 8;
        sdst[it] = (uint32_t)(p * PLANE + r * 64 + ((kc ^ ((r >> 1) & 3)) << 4));
    }

    const int ra = lane & 15;
    const int ksel_a = lane >> 4;
    int rowA[2], swzA[2];
#pragma unroll
    for (int f = 0; f < 2; f++) {
        rowA[f] = mw * 32 + f * 16 + ra;
        swzA[f] = (rowA[f] >> 1) & 3;
    }
    const int rb = (lane & 7) + 8 * (lane >> 4);
    const int ksel_b = (lane >> 3) & 1;
    int rowB[4], swzB[4];
#pragma unroll
    for (int g = 0; g < 4; g++) {
        rowB[g] = nw * 64 + g * 16 + rb;
        swzB[g] = (rowB[g] >> 1) & 3;
    }

    float acc[2][8][4] = {};

#pragma unroll
    for (int pt = 0; pt < 2; pt++) {
        uint32_t sb = sbase + pt * STAGE_BYTES;
#pragma unroll
        for (int it = 0; it < 8; it++) cpa16(sb + sdst[it], gsrc[it] + pt * 32);
        cpa_commit();
    }

    for (int t = 0; t < NCH; t++) {
        cpa_wait<1>();
        __syncthreads();

        if (t + 2 < NCH) {
            uint32_t sb = sbase + ((t + 2) % NSTAGE) * STAGE_BYTES;
#pragma unroll
            for (int it = 0; it < 8; it++) cpa16(sb + sdst[it], gsrc[it] + (t + 2) * 32);
        }
        cpa_commit();

        const uint32_t sb = sbase + (t % NSTAGE) * STAGE_BYTES;
#pragma unroll
        for (int s16 = 0; s16 < 2; s16++) {
            uint32_t ah[2][4], al[2][4];
#pragma unroll
            for (int f = 0; f < 2; f++) {
                uint32_t off = (uint32_t)(rowA[f] * 64 +
                               (((2 * s16 + ksel_a) ^ swzA[f]) << 4));
                ldm4(ah[f], sb + off);
                ldm4(al[f], sb + PLANE + off);
            }
#pragma unroll
            for (int g = 0; g < 4; g++) {
                uint32_t offb = (uint32_t)(rowB[g] * 64 +
                                (((2 * s16 + ksel_b) ^ swzB[g]) << 4));
                uint32_t bh[4], bl[4];
                ldm4(bh, sb + 2 * PLANE + offb);
                ldm4(bl, sb + 3 * PLANE + offb);
                // pass-outer: same-accumulator mma are 4 apart
#pragma unroll
                for (int p = 0; p < 3; p++) {
#pragma unroll
                    for (int f = 0; f < 2; f++) {
                        const uint32_t* A = (p == 2) ? al[f] : ah[f];
                        const uint32_t* Bv = (p == 1) ? bl : bh;
#pragma unroll
                        for (int j = 0; j < 2; j++)
                            mma16(acc[f][g * 2 + j], A, Bv[2 * j], Bv[2 * j + 1]);
                    }
                }
            }
        }
    }

    const int er = lane >> 2, ec = (lane & 3) * 2;
#pragma unroll
    for (int f = 0; f < 2; f++) {
        int r = m0 + mw * 32 + f * 16 + er;
#pragma unroll
        for (int j8 = 0; j8 < 8; j8++) {
            int cc = n0 + nw * 64 + j8 * 8 + ec;
            if (Ch) {
                uint32_t lo0, lo1;
                uint32_t hi0 = pkf(acc[f][j8][0], acc[f][j8][1], &lo0);
                uint32_t hi1 = pkf(acc[f][j8][2], acc[f][j8][3], &lo1);
                *(uint32_t*)(Ch + (size_t)r * N + cc) = hi0;
                *(uint32_t*)(Cl + (size_t)r * N + cc) = lo0;
                *(uint32_t*)(Ch + (size_t)(r + 8) * N + cc) = hi1;
                *(uint32_t*)(Cl + (size_t)(r + 8) * N + cc) = lo1;
            } else {
                *(float2*)(C + (size_t)r * N + cc) =
                    make_float2(acc[f][j8][0], acc[f][j8][1]);
                *(float2*)(C + (size_t)(r + 8) * N + cc) =
                    make_float2(acc[f][j8][2], acc[f][j8][3]);
            }
        }
    }
}

// ---------------------------------------------------------------------------
// bf16 mma flash attention, pass-interleaved (same-acc distance 4 via pairs).
// ---------------------------------------------------------------------------
#define AQ 128
#define AKV 64
#define QH_OFF   0
#define QL_OFF   16384
#define ST_OFF   32768
#define AST      32768
#define QSC_OFF  (ST_OFF + 2 * AST)
#define ATTN2_SMEM (QSC_OFF + 256)

__global__ __launch_bounds__(256)
void attn_mma2(const float* __restrict__ qm,
               const __nv_bfloat16* __restrict__ qkvh,
               const __nv_bfloat16* __restrict__ qkvl,
               __nv_bfloat16* __restrict__ yh,
               __nv_bfloat16* __restrict__ yl)
{
    extern __shared__ char smem[];
    const uint32_t sb = (uint32_t)__cvta_generic_to_shared(smem);
    float* qsc = (float*)(smem + QSC_OFF);
    const int tid = threadIdx.x, lane = tid & 31, warp = tid >> 5;
    const int qt = blockIdx.x, h = blockIdx.y, b = blockIdx.z;
    const int q0 = qt * AQ;

    if (tid < 64) qsc[tid] = logf(2048.0f) * qm[tid] * rsqrtf(64.0f);

    const __nv_bfloat16* kvsrc[8];
    uint32_t kvdst[8];
#pragma unroll
    for (int it = 0; it < 8; it++) {
        int c = tid + it * 256;
        int p = c >> 9, r = (c >> 3) & 63, ch = c & 7;
        const __nv_bfloat16* bp = (p & 1) ? qkvl : qkvh;
        int col = ((p >> 1) ? 2 * C_DIM : C_DIM) + h * DH + ch * 8;
        kvsrc[it] = bp + (size_t)(b * T_SEQ + r) * C3 + col;
        kvdst[it] = (uint32_t)(p * 8192 + r * 128 + ((ch ^ (r & 7)) << 4));
    }
#pragma unroll
    for (int it = 0; it < 8; it++) cpa16(sb + ST_OFF + kvdst[it], kvsrc[it]);
    cpa_commit();

    __syncthreads();

#pragma unroll
    for (int it = 0; it < 4; it++) {
        int u = tid + it * 256;
        int r = u >> 3, ch = u & 7;
        size_t src = (size_t)(b * T_SEQ + q0 + r) * C3 + h * DH + ch * 8;
        uint4 hv = *(const uint4*)(qkvh + src);
        uint4 lv = *(const uint4*)(qkvl + src);
        const __nv_bfloat162* hp = (const __nv_bfloat162*)&hv;
        const __nv_bfloat162* lp = (const __nv_bfloat162*)&lv;
        uint32_t oh[4], ol[4];
#pragma unroll
        for (int k = 0; k < 4; k++) {
            float2 hf = __bfloat1622float2(hp[k]);
            float2 lf = __bfloat1622float2(lp[k]);
            float v0 = (hf.x + lf.x) * qsc[ch * 8 + 2 * k];
            float v1 = (hf.y + lf.y) * qsc[ch * 8 + 2 * k + 1];
            oh[k] = pkf(v0, v1, &ol[k]);
        }
        uint32_t off = (uint32_t)(r * 128 + ((ch ^ (r & 7)) << 4));
        *(uint4*)(smem + QH_OFF + off) = make_uint4(oh[0], oh[1], oh[2], oh[3]);
        *(uint4*)(smem + QL_OFF + off) = make_uint4(ol[0], ol[1], ol[2], ol[3]);
    }

    float m0 = -1e30f, m1 = -1e30f, l0 = 0.0f, l1 = 0.0f;
    float acc[8][4] = {};

    const int maxc = (q0 + AQ > MEMLEN) ? (q0 + AQ) : MEMLEN;
    const int nT = maxc / AKV;

    for (int t = 0; t < nT; t++) {
        cpa_wait<0>();
        __syncthreads();
        if (t + 1 < nT) {
            uint32_t stb = sb + ST_OFF + ((t + 1) & 1) * AST;
            size_t delta = (size_t)(t + 1) * AKV * C3;
#pragma unroll
            for (int it = 0; it < 8; it++) cpa16(stb + kvdst[it], kvsrc[it] + delta);
            cpa_commit();
        }
        const uint32_t st = sb + ST_OFF + (t & 1) * AST;

        // ---- S = Q K^T (3-pass), jj processed in pairs for acc distance 4 ----
        float s_[8][4] = {};
#pragma unroll
        for (int kk = 0; kk < 4; kk++) {
            uint32_t aH[4], aL[4];
            {
                int row = 16 * warp + (lane & 15);
                int ch = kk * 2 + (lane >> 4);
                uint32_t off = (uint32_t)(row * 128 + ((ch ^ (row & 7)) << 4));
                ldm4(aH, sb + QH_OFF + off);
                ldm4(aL, sb + QL_OFF + off);
            }
#pragma unroll
            for (int jp = 0; jp < 2; jp++) {
                uint32_t bH[2][4], bL[2][4];
#pragma unroll
                for (int q = 0; q < 2; q++) {
                    int jj = jp * 2 + q;
                    int row = 16 * jj + 8 * (lane >> 4) + (lane & 7);
                    int ch = kk * 2 + ((lane >> 3) & 1);
                    uint32_t off = (uint32_t)(row * 128 + ((ch ^ (row & 7)) << 4));
                    ldm4(bH[q], st + off);
                    ldm4(bL[q], st + 8192 + off);
                }
#pragma unroll
                for (int p = 0; p < 3; p++) {
                    const uint32_t* A = (p == 2) ? aL : aH;
#pragma unroll
                    for (int q = 0; q < 2; q++) {
                        const uint32_t* Bv = (p == 1) ? bL[q] : bH[q];
#pragma unroll
                        for (int u = 0; u < 2; u++)
                            mma16(s_[2 * (jp * 2 + q) + u], A, Bv[2 * u], Bv[2 * u + 1]);
                    }
                }
            }
        }

        const int kj0 = t * AKV;
        if (kj0 >= MEMLEN) {
            int r0g = q0 + 16 * warp + (lane >> 2);
            int cb = kj0 + 2 * (lane & 3);
#pragma unroll
            for (int j = 0; j < 8; j++) {
                int cg = cb + 8 * j;
                if (cg > r0g)         s_[j][0] = -1e30f;
                if (cg + 1 > r0g)     s_[j][1] = -1e30f;
                if (cg > r0g + 8)     s_[j][2] = -1e30f;
                if (cg + 1 > r0g + 8) s_[j][3] = -1e30f;
            }
        }

        // ---- online softmax ----
        float mx0 = -1e30f, mx1 = -1e30f;
#pragma unroll
        for (int j = 0; j < 8; j++) {
            mx0 = fmaxf(mx0, fmaxf(s_[j][0], s_[j][1]));
            mx1 = fmaxf(mx1, fmaxf(s_[j][2], s_[j][3]));
        }
        mx0 = fmaxf(mx0, __shfl_xor_sync(0xffffffffu, mx0, 1));
        mx0 = fmaxf(mx0, __shfl_xor_sync(0xffffffffu, mx0, 2));
        mx1 = fmaxf(mx1, __shfl_xor_sync(0xffffffffu, mx1, 1));
        mx1 = fmaxf(mx1, __shfl_xor_sync(0xffffffffu, mx1, 2));
        float mn0 = fmaxf(m0, mx0), mn1 = fmaxf(m1, mx1);
        float f0 = __expf(m0 - mn0), f1 = __expf(m1 - mn1);
        float sum0 = 0.0f, sum1 = 0.0f;
        uint32_t phA[8], phB[8], plA[8], plB[8];
#pragma unroll
        for (int j = 0; j < 8; j++) {
            float p0 = __expf(s_[j][0] - mn0);
            float p1 = __expf(s_[j][1] - mn0);
            float p2 = __expf(s_[j][2] - mn1);
            float p3 = __expf(s_[j][3] - mn1);
            sum0 += p0 + p1; sum1 += p2 + p3;
            phA[j] = pkf(p0, p1, &plA[j]);
            phB[j] = pkf(p2, p3, &plB[j]);
        }
        sum0 += __shfl_xor_sync(0xffffffffu, sum0, 1);
        sum0 += __shfl_xor_sync(0xffffffffu, sum0, 2);
        sum1 += __shfl_xor_sync(0xffffffffu, sum1, 1);
        sum1 += __shfl_xor_sync(0xffffffffu, sum1, 2);
        l0 = l0 * f0 + sum0; l1 = l1 * f1 + sum1;
        m0 = mn0; m1 = mn1;
#pragma unroll
        for (int j = 0; j < 8; j++) {
            acc[j][0] *= f0; acc[j][1] *= f0;
            acc[j][2] *= f1; acc[j][3] *= f1;
        }

        // ---- P @ V (3-pass), nn in pairs for acc distance 4 ----
#pragma unroll
        for (int jj = 0; jj < 4; jj++) {
            uint32_t pa[4] = {phA[2*jj], phB[2*jj], phA[2*jj+1], phB[2*jj+1]};
            uint32_t pb[4] = {plA[2*jj], plB[2*jj], plA[2*jj+1], plB[2*jj+1]};
#pragma unroll
            for (int np = 0; np < 2; np++) {
                uint32_t vH[2][4], vL[2][4];
#pragma unroll
                for (int q = 0; q < 2; q++) {
                    int nn = np * 2 + q;
                    int row = 16 * jj + 8 * ((lane >> 3) & 1) + (lane & 7);
                    int ch = 2 * nn + (lane >> 4);
                    uint32_t off = (uint32_t)(row * 128 + ((ch ^ (row & 7)) << 4));
                    ldm4t(vH[q], st + 16384 + off);
                    ldm4t(vL[q], st + 24576 + off);
                }
#pragma unroll
                for (int p = 0; p < 3; p++) {
                    const uint32_t* P = (p == 2) ? pb : pa;
#pragma unroll
                    for (int q = 0; q < 2; q++) {
                        const uint32_t* Vv = (p == 1) ? vL[q] : vH[q];
#pragma unroll
                        for (int u = 0; u < 2; u++)
                            mma16(acc[2 * (np * 2 + q) + u], P, Vv[2 * u], Vv[2 * u + 1]);
                    }
                }
            }
        }
    }

    // ---- epilogue ----
    {
        float i0 = 1.0f / l0, i1 = 1.0f / l1;
        size_t r0 = (size_t)(b * T_SEQ + q0 + 16 * warp + (lane >> 2));
        int cb = h * DH + 2 * (lane & 3);
#pragma unroll
        for (int j = 0; j < 8; j++) {
            int cc = cb + 8 * j;
            uint32_t lo0, lo1;
            uint32_t hi0 = pkf(acc[j][0] * i0, acc[j][1] * i0, &lo0);
            uint32_t hi1 = pkf(acc[j][2] * i1, acc[j][3] * i1, &lo1);
            *(uint32_t*)(yh + r0 * C_DIM + cc) = hi0;
            *(uint32_t*)(yl + r0 * C_DIM + cc) = lo0;
            *(uint32_t*)(yh + (r0 + 8) * C_DIM + cc) = hi1;
            *(uint32_t*)(yl + (r0 + 8) * C_DIM + cc) = lo1;
        }
    }
}

// ---------------------------------------------------------------------------
// Launch
// ---------------------------------------------------------------------------
extern "C" void kernel_launch(void* const* d_in, const int* in_sizes, int n_in,
                              void* d_out, int out_size)
{
    const float* x      = (const float*)d_in[0];
    const float* w_qkv  = (const float*)d_in[1];
    const float* w_proj = (const float*)d_in[2];
    const float* qm     = (const float*)d_in[3];
    float* out = (float*)d_out;

    static __nv_bfloat16 *p_xh = nullptr, *p_xl, *p_wqh, *p_wql, *p_wph, *p_wpl;
    static __nv_bfloat16 *p_qkvh, *p_qkvl, *p_yh, *p_yl;
    if (!p_xh) {
        cudaGetSymbolAddress((void**)&p_xh, g_xh);
        cudaGetSymbolAddress((void**)&p_xl, g_xl);
        cudaGetSymbolAddress((void**)&p_wqh, g_wqh);
        cudaGetSymbolAddress((void**)&p_wql, g_wql);
        cudaGetSymbolAddress((void**)&p_wph, g_wph);
        cudaGetSymbolAddress((void**)&p_wpl, g_wpl);
        cudaGetSymbolAddress((void**)&p_qkvh, g_qkvh);
        cudaGetSymbolAddress((void**)&p_qkvl, g_qkvl);
        cudaGetSymbolAddress((void**)&p_yh, g_yh);
        cudaGetSymbolAddress((void**)&p_yl, g_yl);
        cudaFuncSetAttribute(gemm_bf16_kernel,
                             cudaFuncAttributeMaxDynamicSharedMemorySize, GEMM_SMEM);
        cudaFuncSetAttribute(attn_mma2,
                             cudaFuncAttributeMaxDynamicSharedMemorySize, ATTN2_SMEM);
    }

    // Split fp32 inputs into bf16 hi/lo planes
    split_kernel<<<(M_TOT * KD / 8 + 255) / 256, 256>>>(x, p_xh, p_xl, M_TOT * KD / 8);
    split_kernel<<<(C3 * KD / 8 + 255) / 256, 256>>>(w_qkv, p_wqh, p_wql, C3 * KD / 8);
    split_kernel<<<(C_DIM * KD / 8 + 255) / 256, 256>>>(w_proj, p_wph, p_wpl, C_DIM * KD / 8);

    // GEMM1: qkv = x @ w_qkv^T -> bf16 hi/lo planes
    {
        dim3 grid(C3 / 128, M_TOT / 128);
        gemm_bf16_kernel<<<grid, 256, GEMM_SMEM>>>(p_xh, p_xl, p_wqh, p_wql,
                                                   nullptr, p_qkvh, p_qkvl, C3);
    }

    // Fused attention -> y hi/lo planes
    {
        dim3 grid(T_SEQ / AQ, NH, B_SZ);
        attn_mma2<<<grid, 256, ATTN2_SMEM>>>(qm, p_qkvh, p_qkvl, p_yh, p_yl);
    }

    // GEMM2: out = y @ w_proj^T -> fp32
    {
        dim3 grid(C_DIM / 128, M_TOT / 128);
        gemm_bf16_kernel<<<grid, 256, GEMM_SMEM>>>(p_yh, p_yl, p_wph, p_wpl,
                                                   out, nullptr, nullptr, C_DIM);
    }
}

// round 8
// speedup vs baseline: 4.7182x; 1.0985x over previous
#include <cuda_runtime.h>
#include <cuda_fp16.h>
#include <math.h>
#include <stdint.h>

// Problem constants
#define B_SZ   2
#define T_SEQ  2048
#define C_DIM  1024
#define C3     3072
#define NH     16
#define DH     64
#define MEMLEN 1024
#define M_TOT  4096
#define KD     1024

// Scratch fp16 hi/lo planes (no cudaMalloc allowed)
__device__ __half g_xh[(size_t)M_TOT * KD];
__device__ __half g_xl[(size_t)M_TOT * KD];
__device__ __half g_wqh[(size_t)C3 * KD];
__device__ __half g_wql[(size_t)C3 * KD];
__device__ __half g_wph[(size_t)C_DIM * KD];
__device__ __half g_wpl[(size_t)C_DIM * KD];
__device__ __half g_qkvh[(size_t)M_TOT * C3];
__device__ __half g_qkvl[(size_t)M_TOT * C3];
__device__ __half g_yh[(size_t)M_TOT * KD];

// ---------------------------------------------------------------------------
// helpers
// ---------------------------------------------------------------------------
__device__ __forceinline__ uint32_t pk2(__half a, __half b) {
    __half2 t = __halves2half2(a, b);
    return *reinterpret_cast<uint32_t*>(&t);
}

__device__ __forceinline__ uint32_t pkh(float a, float b) {
    __half2 t = __floats2half2_rn(a, b);
    return *reinterpret_cast<uint32_t*>(&t);
}

__device__ __forceinline__ uint32_t pkf(float a, float b, uint32_t* lo) {
    __half ha = __float2half_rn(a), hb = __float2half_rn(b);
    __half la = __float2half_rn(a - __half2float(ha));
    __half lb = __float2half_rn(b - __half2float(hb));
    *lo = pk2(la, lb);
    return pk2(ha, hb);
}

__device__ __forceinline__ void ldm4(uint32_t r[4], uint32_t a) {
    asm volatile("ldmatrix.sync.aligned.m8n8.x4.shared.b16 {%0,%1,%2,%3},[%4];\n"
                 : "=r"(r[0]), "=r"(r[1]), "=r"(r[2]), "=r"(r[3]) : "r"(a));
}
__device__ __forceinline__ void ldm4t(uint32_t r[4], uint32_t a) {
    asm volatile("ldmatrix.sync.aligned.m8n8.x4.trans.shared.b16 {%0,%1,%2,%3},[%4];\n"
                 : "=r"(r[0]), "=r"(r[1]), "=r"(r[2]), "=r"(r[3]) : "r"(a));
}

__device__ __forceinline__ void mma16(float d[4], const uint32_t a[4],
                                      uint32_t b0, uint32_t b1) {
    asm volatile(
        "mma.sync.aligned.m16n8k16.row.col.f32.f16.f16.f32 "
        "{%0,%1,%2,%3},{%4,%5,%6,%7},{%8,%9},{%0,%1,%2,%3};\n"
        : "+f"(d[0]), "+f"(d[1]), "+f"(d[2]), "+f"(d[3])
        : "r"(a[0]), "r"(a[1]), "r"(a[2]), "r"(a[3]), "r"(b0), "r"(b1));
}

__device__ __forceinline__ void cpa16(uint32_t d, const void* g) {
    asm volatile("cp.async.cg.shared.global [%0], [%1], 16;" :: "r"(d), "l"(g) : "memory");
}
__device__ __forceinline__ void cpa_commit() {
    asm volatile("cp.async.commit_group;" ::: "memory");
}
template <int N>
__device__ __forceinline__ void cpa_wait() {
    asm volatile("cp.async.wait_group %0;" :: "n"(N) : "memory");
}

// ---------------------------------------------------------------------------
// Split fp32 -> fp16 hi/lo planes
// ---------------------------------------------------------------------------
__global__ __launch_bounds__(256)
void split_kernel(const float* __restrict__ src,
                  __half* __restrict__ hi,
                  __half* __restrict__ lo, int n8)
{
    int i = blockIdx.x * 256 + threadIdx.x;
    if (i >= n8) return;
    float4 v0 = ((const float4*)src)[2 * i];
    float4 v1 = ((const float4*)src)[2 * i + 1];
    float v[8] = {v0.x, v0.y, v0.z, v0.w, v1.x, v1.y, v1.z, v1.w};
    uint32_t hp[4], lp[4];
#pragma unroll
    for (int j = 0; j < 4; j++)
        hp[j] = pkf(v[2 * j], v[2 * j + 1], &lp[j]);
    ((uint4*)hi)[i] = make_uint4(hp[0], hp[1], hp[2], hp[3]);
    ((uint4*)lo)[i] = make_uint4(lp[0], lp[1], lp[2], lp[3]);
}

// ---------------------------------------------------------------------------
// fp16 split NT GEMM: blocks with n0 < fullN use 3-mma (drop ll), others
// 2-mma (A single-rounded).  C fp32 or fp16 hi/lo planes.
// ---------------------------------------------------------------------------
#define PLANE        8192
#define STAGE_BYTES  32768
#define NSTAGE       3
#define GEMM_SMEM    (NSTAGE * STAGE_BYTES)
#define NCH          32

__global__ __launch_bounds__(256, 2)
void gemm_fp16_kernel(const __half* __restrict__ Ah,
                      const __half* __restrict__ Al,
                      const __half* __restrict__ Bh,
                      const __half* __restrict__ Bl,
                      float* __restrict__ C,
                      __half* __restrict__ Ch,
                      __half* __restrict__ Cl, int N, int fullN)
{
    extern __shared__ char smem[];
    const uint32_t sbase = (uint32_t)__cvta_generic_to_shared(smem);
    const int tid = threadIdx.x, lane = tid & 31, warp = tid >> 5;
    const int m0 = blockIdx.y * 128, n0 = blockIdx.x * 128;
    const bool full = (n0 < fullN);
    const int mw = warp >> 1, nw = warp & 1;

    const __half* gsrc[8];
    uint32_t sdst[8];
#pragma unroll
    for (int it = 0; it < 8; it++) {
        int c = tid + it * 256;
        int p = c >> 9;
        int r = (c >> 2) & 127;
        int kc = c & 3;
        const __half* bp = (p == 0) ? Ah : (p == 1) ? Al : (p == 2) ? Bh : Bl;
        int row = ((p < 2) ? m0 : n0) + r;
        gsrc[it] = bp + (size_t)row * KD + kc * 8;
        sdst[it] = (uint32_t)(p * PLANE + r * 64 + ((kc ^ ((r >> 1) & 3)) << 4));
    }

    const int ra = lane & 15;
    const int ksel_a = lane >> 4;
    int rowA[2], swzA[2];
#pragma unroll
    for (int f = 0; f < 2; f++) {
        rowA[f] = mw * 32 + f * 16 + ra;
        swzA[f] = (rowA[f] >> 1) & 3;
    }
    const int rb = (lane & 7) + 8 * (lane >> 4);
    const int ksel_b = (lane >> 3) & 1;
    int rowB[4], swzB[4];
#pragma unroll
    for (int g = 0; g < 4; g++) {
        rowB[g] = nw * 64 + g * 16 + rb;
        swzB[g] = (rowB[g] >> 1) & 3;
    }

    float acc[2][8][4] = {};

#pragma unroll
    for (int pt = 0; pt < 2; pt++) {
        uint32_t sb = sbase + pt * STAGE_BYTES;
#pragma unroll
        for (int it = 0; it < 8; it++) cpa16(sb + sdst[it], gsrc[it] + pt * 32);
        cpa_commit();
    }

    for (int t = 0; t < NCH; t++) {
        cpa_wait<1>();
        __syncthreads();

        if (t + 2 < NCH) {
            uint32_t sb = sbase + ((t + 2) % NSTAGE) * STAGE_BYTES;
#pragma unroll
            for (int it = 0; it < 8; it++) cpa16(sb + sdst[it], gsrc[it] + (t + 2) * 32);
        }
        cpa_commit();

        const uint32_t sb = sbase + (t % NSTAGE) * STAGE_BYTES;
#pragma unroll
        for (int s16 = 0; s16 < 2; s16++) {
            uint32_t ah[2][4], al[2][4];
#pragma unroll
            for (int f = 0; f < 2; f++) {
                uint32_t off = (uint32_t)(rowA[f] * 64 +
                               (((2 * s16 + ksel_a) ^ swzA[f]) << 4));
                ldm4(ah[f], sb + off);
                if (full) ldm4(al[f], sb + PLANE + off);
            }
#pragma unroll
            for (int g = 0; g < 4; g++) {
                uint32_t offb = (uint32_t)(rowB[g] * 64 +
                                (((2 * s16 + ksel_b) ^ swzB[g]) << 4));
                uint32_t bh[4], bl[4];
                ldm4(bh, sb + 2 * PLANE + offb);
                ldm4(bl, sb + 3 * PLANE + offb);
#pragma unroll
                for (int f = 0; f < 2; f++) {
#pragma unroll
                    for (int j = 0; j < 2; j++) {
                        float* d = acc[f][g * 2 + j];
                        mma16(d, ah[f], bh[2 * j], bh[2 * j + 1]);
                        mma16(d, ah[f], bl[2 * j], bl[2 * j + 1]);
                        if (full) mma16(d, al[f], bh[2 * j], bh[2 * j + 1]);
                    }
                }
            }
        }
    }

    const int er = lane >> 2, ec = (lane & 3) * 2;
#pragma unroll
    for (int f = 0; f < 2; f++) {
        int r = m0 + mw * 32 + f * 16 + er;
#pragma unroll
        for (int j8 = 0; j8 < 8; j8++) {
            int cc = n0 + nw * 64 + j8 * 8 + ec;
            if (Ch) {
                uint32_t lo0, lo1;
                uint32_t hi0 = pkf(acc[f][j8][0], acc[f][j8][1], &lo0);
                uint32_t hi1 = pkf(acc[f][j8][2], acc[f][j8][3], &lo1);
                *(uint32_t*)(Ch + (size_t)r * N + cc) = hi0;
                *(uint32_t*)(Cl + (size_t)r * N + cc) = lo0;
                *(uint32_t*)(Ch + (size_t)(r + 8) * N + cc) = hi1;
                *(uint32_t*)(Cl + (size_t)(r + 8) * N + cc) = lo1;
            } else {
                *(float2*)(C + (size_t)r * N + cc) =
                    make_float2(acc[f][j8][0], acc[f][j8][1]);
                *(float2*)(C + (size_t)(r + 8) * N + cc) =
                    make_float2(acc[f][j8][2], acc[f][j8][3]);
            }
        }
    }
}

// ---------------------------------------------------------------------------
// fp16 mma flash attention: S 3-mma, PV 2-mma (P single fp16).
// Writes y as single fp16 plane (GEMM2 is 2-mma).
// ---------------------------------------------------------------------------
#define AQ 128
#define AKV 64
#define QH_OFF   0
#define QL_OFF   16384
#define ST_OFF   32768
#define AST      32768
#define QSC_OFF  (ST_OFF + 2 * AST)
#define ATTN2_SMEM (QSC_OFF + 256)

__global__ __launch_bounds__(256)
void attn_mma2(const float* __restrict__ qm,
               const __half* __restrict__ qkvh,
               const __half* __restrict__ qkvl,
               __half* __restrict__ yh)
{
    extern __shared__ char smem[];
    const uint32_t sb = (uint32_t)__cvta_generic_to_shared(smem);
    float* qsc = (float*)(smem + QSC_OFF);
    const int tid = threadIdx.x, lane = tid & 31, warp = tid >> 5;
    const int qt = blockIdx.x, h = blockIdx.y, b = blockIdx.z;
    const int q0 = qt * AQ;

    if (tid < 64) qsc[tid] = logf(2048.0f) * qm[tid] * rsqrtf(64.0f);

    const __half* kvsrc[8];
    uint32_t kvdst[8];
#pragma unroll
    for (int it = 0; it < 8; it++) {
        int c = tid + it * 256;
        int p = c >> 9, r = (c >> 3) & 63, ch = c & 7;
        const __half* bp = (p & 1) ? qkvl : qkvh;
        int col = ((p >> 1) ? 2 * C_DIM : C_DIM) + h * DH + ch * 8;
        kvsrc[it] = bp + (size_t)(b * T_SEQ + r) * C3 + col;
        kvdst[it] = (uint32_t)(p * 8192 + r * 128 + ((ch ^ (r & 7)) << 4));
    }
#pragma unroll
    for (int it = 0; it < 8; it++) cpa16(sb + ST_OFF + kvdst[it], kvsrc[it]);
    cpa_commit();

    __syncthreads();

#pragma unroll
    for (int it = 0; it < 4; it++) {
        int u = tid + it * 256;
        int r = u >> 3, ch = u & 7;
        size_t src = (size_t)(b * T_SEQ + q0 + r) * C3 + h * DH + ch * 8;
        uint4 hv = *(const uint4*)(qkvh + src);
        uint4 lv = *(const uint4*)(qkvl + src);
        const __half2* hp = (const __half2*)&hv;
        const __half2* lp = (const __half2*)&lv;
        uint32_t oh[4], ol[4];
#pragma unroll
        for (int k = 0; k < 4; k++) {
            float2 hf = __half22float2(hp[k]);
            float2 lf = __half22float2(lp[k]);
            float v0 = (hf.x + lf.x) * qsc[ch * 8 + 2 * k];
            float v1 = (hf.y + lf.y) * qsc[ch * 8 + 2 * k + 1];
            oh[k] = pkf(v0, v1, &ol[k]);
        }
        uint32_t off = (uint32_t)(r * 128 + ((ch ^ (r & 7)) << 4));
        *(uint4*)(smem + QH_OFF + off) = make_uint4(oh[0], oh[1], oh[2], oh[3]);
        *(uint4*)(smem + QL_OFF + off) = make_uint4(ol[0], ol[1], ol[2], ol[3]);
    }

    float m0 = -1e30f, m1 = -1e30f, l0 = 0.0f, l1 = 0.0f;
    float acc[8][4] = {};

    const int maxc = (q0 + AQ > MEMLEN) ? (q0 + AQ) : MEMLEN;
    const int nT = maxc / AKV;

    for (int t = 0; t < nT; t++) {
        cpa_wait<0>();
        __syncthreads();
        if (t + 1 < nT) {
            uint32_t stb = sb + ST_OFF + ((t + 1) & 1) * AST;
            size_t delta = (size_t)(t + 1) * AKV * C3;
#pragma unroll
            for (int it = 0; it < 8; it++) cpa16(stb + kvdst[it], kvsrc[it] + delta);
            cpa_commit();
        }
        const uint32_t st = sb + ST_OFF + (t & 1) * AST;

        // ---- S = Q K^T (3-mma fp16) ----
        float s_[8][4] = {};
#pragma unroll
        for (int kk = 0; kk < 4; kk++) {
            uint32_t aH[4], aL[4];
            {
                int row = 16 * warp + (lane & 15);
                int ch = kk * 2 + (lane >> 4);
                uint32_t off = (uint32_t)(row * 128 + ((ch ^ (row & 7)) << 4));
                ldm4(aH, sb + QH_OFF + off);
                ldm4(aL, sb + QL_OFF + off);
            }
#pragma unroll
            for (int jj = 0; jj < 4; jj++) {
                int row = 16 * jj + 8 * (lane >> 4) + (lane & 7);
                int ch = kk * 2 + ((lane >> 3) & 1);
                uint32_t off = (uint32_t)(row * 128 + ((ch ^ (row & 7)) << 4));
                uint32_t bH[4], bL[4];
                ldm4(bH, st + off);
                ldm4(bL, st + 8192 + off);
#pragma unroll
                for (int u = 0; u < 2; u++) {
                    float* d = s_[2 * jj + u];
                    mma16(d, aH, bH[2 * u], bH[2 * u + 1]);
                    mma16(d, aH, bL[2 * u], bL[2 * u + 1]);
                    mma16(d, aL, bH[2 * u], bH[2 * u + 1]);
                }
            }
        }

        const int kj0 = t * AKV;
        if (kj0 >= MEMLEN) {
            int r0g = q0 + 16 * warp + (lane >> 2);
            int cb = kj0 + 2 * (lane & 3);
#pragma unroll
            for (int j = 0; j < 8; j++) {
                int cg = cb + 8 * j;
                if (cg > r0g)         s_[j][0] = -1e30f;
                if (cg + 1 > r0g)     s_[j][1] = -1e30f;
                if (cg > r0g + 8)     s_[j][2] = -1e30f;
                if (cg + 1 > r0g + 8) s_[j][3] = -1e30f;
            }
        }

        // ---- online softmax ----
        float mx0 = -1e30f, mx1 = -1e30f;
#pragma unroll
        for (int j = 0; j < 8; j++) {
            mx0 = fmaxf(mx0, fmaxf(s_[j][0], s_[j][1]));
            mx1 = fmaxf(mx1, fmaxf(s_[j][2], s_[j][3]));
        }
        mx0 = fmaxf(mx0, __shfl_xor_sync(0xffffffffu, mx0, 1));
        mx0 = fmaxf(mx0, __shfl_xor_sync(0xffffffffu, mx0, 2));
        mx1 = fmaxf(mx1, __shfl_xor_sync(0xffffffffu, mx1, 1));
        mx1 = fmaxf(mx1, __shfl_xor_sync(0xffffffffu, mx1, 2));
        float mn0 = fmaxf(m0, mx0), mn1 = fmaxf(m1, mx1);
        float f0 = __expf(m0 - mn0), f1 = __expf(m1 - mn1);
        float sum0 = 0.0f, sum1 = 0.0f;
        uint32_t phA[8], phB[8];
#pragma unroll
        for (int j = 0; j < 8; j++) {
            float p0 = __expf(s_[j][0] - mn0);
            float p1 = __expf(s_[j][1] - mn0);
            float p2 = __expf(s_[j][2] - mn1);
            float p3 = __expf(s_[j][3] - mn1);
            sum0 += p0 + p1; sum1 += p2 + p3;
            phA[j] = pkh(p0, p1);
            phB[j] = pkh(p2, p3);
        }
        sum0 += __shfl_xor_sync(0xffffffffu, sum0, 1);
        sum0 += __shfl_xor_sync(0xffffffffu, sum0, 2);
        sum1 += __shfl_xor_sync(0xffffffffu, sum1, 1);
        sum1 += __shfl_xor_sync(0xffffffffu, sum1, 2);
        l0 = l0 * f0 + sum0; l1 = l1 * f1 + sum1;
        m0 = mn0; m1 = mn1;
#pragma unroll
        for (int j = 0; j < 8; j++) {
            acc[j][0] *= f0; acc[j][1] *= f0;
            acc[j][2] *= f1; acc[j][3] *= f1;
        }

        // ---- P @ V (2-mma: P single fp16, V hi/lo) ----
#pragma unroll
        for (int jj = 0; jj < 4; jj++) {
            uint32_t pa[4] = {phA[2*jj], phB[2*jj], phA[2*jj+1], phB[2*jj+1]};
#pragma unroll
            for (int nn = 0; nn < 4; nn++) {
                int row = 16 * jj + 8 * ((lane >> 3) & 1) + (lane & 7);
                int ch = 2 * nn + (lane >> 4);
                uint32_t off = (uint32_t)(row * 128 + ((ch ^ (row & 7)) << 4));
                uint32_t vH[4], vL[4];
                ldm4t(vH, st + 16384 + off);
                ldm4t(vL, st + 24576 + off);
#pragma unroll
                for (int u = 0; u < 2; u++) {
                    float* d = acc[2 * nn + u];
                    mma16(d, pa, vH[2 * u], vH[2 * u + 1]);
                    mma16(d, pa, vL[2 * u], vL[2 * u + 1]);
                }
            }
        }
    }

    // ---- epilogue: normalize, write y single fp16 plane ----
    {
        float i0 = 1.0f / l0, i1 = 1.0f / l1;
        size_t r0 = (size_t)(b * T_SEQ + q0 + 16 * warp + (lane >> 2));
        int cb = h * DH + 2 * (lane & 3);
#pragma unroll
        for (int j = 0; j < 8; j++) {
            int cc = cb + 8 * j;
            *(uint32_t*)(yh + r0 * C_DIM + cc)       = pkh(acc[j][0] * i0, acc[j][1] * i0);
            *(uint32_t*)(yh + (r0 + 8) * C_DIM + cc) = pkh(acc[j][2] * i1, acc[j][3] * i1);
        }
    }
}

// ---------------------------------------------------------------------------
// Launch
// ---------------------------------------------------------------------------
extern "C" void kernel_launch(void* const* d_in, const int* in_sizes, int n_in,
                              void* d_out, int out_size)
{
    const float* x      = (const float*)d_in[0];
    const float* w_qkv  = (const float*)d_in[1];
    const float* w_proj = (const float*)d_in[2];
    const float* qm     = (const float*)d_in[3];
    float* out = (float*)d_out;

    static __half *p_xh = nullptr, *p_xl, *p_wqh, *p_wql, *p_wph, *p_wpl;
    static __half *p_qkvh, *p_qkvl, *p_yh;
    if (!p_xh) {
        cudaGetSymbolAddress((void**)&p_xh, g_xh);
        cudaGetSymbolAddress((void**)&p_xl, g_xl);
        cudaGetSymbolAddress((void**)&p_wqh, g_wqh);
        cudaGetSymbolAddress((void**)&p_wql, g_wql);
        cudaGetSymbolAddress((void**)&p_wph, g_wph);
        cudaGetSymbolAddress((void**)&p_wpl, g_wpl);
        cudaGetSymbolAddress((void**)&p_qkvh, g_qkvh);
        cudaGetSymbolAddress((void**)&p_qkvl, g_qkvl);
        cudaGetSymbolAddress((void**)&p_yh, g_yh);
        cudaFuncSetAttribute(gemm_fp16_kernel,
                             cudaFuncAttributeMaxDynamicSharedMemorySize, GEMM_SMEM);
        cudaFuncSetAttribute(attn_mma2,
                             cudaFuncAttributeMaxDynamicSharedMemorySize, ATTN2_SMEM);
    }

    // Split fp32 inputs into fp16 hi/lo planes
    split_kernel<<<(M_TOT * KD / 8 + 255) / 256, 256>>>(x, p_xh, p_xl, M_TOT * KD / 8);
    split_kernel<<<(C3 * KD / 8 + 255) / 256, 256>>>(w_qkv, p_wqh, p_wql, C3 * KD / 8);
    split_kernel<<<(C_DIM * KD / 8 + 255) / 256, 256>>>(w_proj, p_wph, p_wpl, C_DIM * KD / 8);

    // GEMM1: qkv = x @ w_qkv^T -> fp16 hi/lo planes.
    // Q,K columns (n0 < 2048): 3-mma; V columns: 2-mma.
    {
        dim3 grid(C3 / 128, M_TOT / 128);
        gemm_fp16_kernel<<<grid, 256, GEMM_SMEM>>>(p_xh, p_xl, p_wqh, p_wql,
                                                   nullptr, p_qkvh, p_qkvl, C3,
                                                   2 * C_DIM);
    }

    // Fused attention -> y single fp16 plane
    {
        dim3 grid(T_SEQ / AQ, NH, B_SZ);
        attn_mma2<<<grid, 256, ATTN2_SMEM>>>(qm, p_qkvh, p_qkvl, p_yh);
    }

    // GEMM2: out = y @ w_proj^T -> fp32, all blocks 2-mma (A = y single fp16)
    {
        dim3 grid(C_DIM / 128, M_TOT / 128);
        gemm_fp16_kernel<<<grid, 256, GEMM_SMEM>>>(p_yh, p_yh, p_wph, p_wpl,
                                                   out, nullptr, nullptr, C_DIM, 0);
    }
}